// round 12
// baseline (speedup 1.0000x reference)
#include <cuda_runtime.h>
#include <cuda_fp16.h>
#include <math.h>
#include <stdint.h>

#define FDIM 128
#define NMAX 50000
#define EMAX 800000
#define KPOST (13*FDIM)   /* 1664 */
#define NT    ((NMAX + 127)/128)   /* 391 m-tiles */
#define PITCH 40                   /* halves per smem/blocked row */
#define BLKH  (128*PITCH)          /* halves per block: 5120 */
#define BLKB  (BLKH*2)             /* bytes per block: 10240 */

// ---------------- scratch (static device globals; no allocation) -------------
__device__ __align__(16) int    g_deg[NMAX];                      // stays zeroed between runs
__device__ __align__(16) int    g_rowptr[NMAX+1];
__device__ __align__(16) int    g_cursor[NMAX];
__device__ __align__(16) int    g_srcs[EMAX];
__device__ __align__(16) float  g_u[(size_t)NMAX*FDIM];
__device__ __align__(16) __half g_vh[(size_t)NMAX*FDIM];          // fp16 v (row-major)
__device__ __align__(16) __half g_xb[(size_t)NT*4*BLKH];          // x, chunk-blocked
__device__ __align__(16) __half g_aggb[(size_t)NT*16*BLKH];       // agg, chunk-blocked
__device__ __align__(16) float  g_amp[NMAX];
__device__ __align__(16) float  g_att[NMAX];
__device__ __align__(16) __half g_wuvb[2*4*BLKH];                 // W_uv, blocked
__device__ __align__(16) float  g_Wt_lin[FDIM*FDIM];              // [128][128] (k-major)
__device__ __align__(16) __half g_wcb[52*BLKH];                   // W_comb, blocked
__device__ __align__(16) float  g_b_comb[FDIM];

__device__ __forceinline__ uint32_t s2u(const void* p){
    return (uint32_t)__cvta_generic_to_shared(p);
}

// ---- cp.async.bulk (non-tensor) + mbarrier ----------------------------------
__device__ __forceinline__ void bulk_g2s(uint32_t dst, const void* src,
                                         uint32_t bytes, uint32_t mbar){
    uint64_t g;
    asm("cvta.to.global.u64 %0, %1;" : "=l"(g) : "l"(src));
    asm volatile(
        "cp.async.bulk.shared::cta.global.mbarrier::complete_tx::bytes "
        "[%0], [%1], %2, [%3];"
        :: "r"(dst), "l"(g), "r"(bytes), "r"(mbar) : "memory");
}
__device__ __forceinline__ void mbar_init(uint32_t mbar, uint32_t cnt){
    asm volatile("mbarrier.init.shared.b64 [%0], %1;" :: "r"(mbar), "r"(cnt) : "memory");
}
__device__ __forceinline__ void mbar_expect_tx(uint32_t mbar, uint32_t bytes){
    asm volatile("mbarrier.arrive.expect_tx.shared.b64 _, [%0], %1;"
                 :: "r"(mbar), "r"(bytes) : "memory");
}
__device__ __forceinline__ void mbar_wait(uint32_t mbar, uint32_t parity){
    uint32_t done = 0;
    while (!done){
        asm volatile(
            "{\n\t"
            ".reg .pred p;\n\t"
            "mbarrier.try_wait.parity.acquire.cta.shared::cta.b64 p, [%1], %2, 0x989680;\n\t"
            "selp.b32 %0, 1, 0, p;\n\t"
            "}"
            : "=r"(done) : "r"(mbar), "r"(parity) : "memory");
    }
}

#define MMA_F16(acc, a0,a1,a2,a3, b0,b1) \
    asm volatile( \
        "mma.sync.aligned.m16n8k16.row.col.f32.f16.f16.f32 " \
        "{%0,%1,%2,%3}, {%4,%5,%6,%7}, {%8,%9}, {%0,%1,%2,%3};\n" \
        : "+f"((acc)[0]), "+f"((acc)[1]), "+f"((acc)[2]), "+f"((acc)[3]) \
        : "r"(a0), "r"(a1), "r"(a2), "r"(a3), "r"(b0), "r"(b1))

#define LDSM_X4(r0,r1,r2,r3,addr) \
    asm volatile("ldmatrix.sync.aligned.m8n8.x4.shared.b16 {%0,%1,%2,%3}, [%4];" \
        : "=r"(r0), "=r"(r1), "=r"(r2), "=r"(r3) : "r"(addr))

#define PREP_BLOCKS 512

// ---------------- K1: hist (blocks < HB) || prep (blocks >= HB) --------------
__global__ void k1_hist_prep(const int* __restrict__ dst, int E, int HB,
                             const float* __restrict__ x,
                             const float* __restrict__ W_pre,
                             const float* __restrict__ W_lin, int N){
    int b = blockIdx.x;
    if (b < HB){
        int e = b*256 + threadIdx.x;
        if (e < E) atomicAdd(&g_deg[dst[e]], 1);
        return;
    }
    int i0 = (b - HB)*256 + threadIdx.x;
    const int stride = PREP_BLOCKS*256;
    for (int i = i0; i < N*FDIM; i += stride){
        int node = i >> 7, col = i & 127;
        g_xb[((size_t)(node >> 7)*4 + (col >> 5))*BLKH + (node & 127)*PITCH + (col & 31)]
            = __float2half_rn(x[i]);
    }
    for (int i = i0; i < 256*128; i += stride){
        int j = i >> 7, k = i & 127;
        float val = W_pre[(size_t)(j & 127)*256 + ((j >> 7) ? (128 + k) : k)];
        g_wuvb[((size_t)(j >> 7)*4 + (k >> 5))*BLKH + (j & 127)*PITCH + (k & 31)]
            = __float2half_rn(val);
    }
    for (int i = i0; i < FDIM*FDIM; i += stride){
        int f = i >> 7, c = i & 127;
        g_Wt_lin[c*FDIM + f] = W_lin[i];
    }
}

// ---------------- K2: scan (block 0) || u/v GEMM (blocks 1..2*gm) ------------
__global__ void __launch_bounds__(256, 2)
k2_scan_uv(int n, int M, int gm, const float* __restrict__ b_pre)
{
    __shared__ __align__(16) __half st[2][2*BLKH];   // uv stages [A | W]
    __shared__ __align__(16) uint64_t barsto[2];
    __shared__ int ss[256];

    int tid = threadIdx.x;

    if (blockIdx.x == 0){
        // ---- exclusive scan of g_deg -> rowptr/cursor; zero g_deg for next run
        int t = tid;
        int chunk = (n + 255) >> 8;
        int lo = t*chunk;
        int hi = min(lo + chunk, n);
        int s = 0;
        for (int i = lo; i < hi; i++) s += g_deg[i];
        ss[t] = s;
        __syncthreads();
        for (int off = 1; off < 256; off <<= 1){
            int v = (t >= off) ? ss[t-off] : 0;
            __syncthreads();
            ss[t] += v;
            __syncthreads();
        }
        int run = (t == 0) ? 0 : ss[t-1];
        for (int i = lo; i < hi; i++){
            g_rowptr[i] = run;
            g_cursor[i] = run;
            run += g_deg[i];
            g_deg[i] = 0;
        }
        if (t == 255) g_rowptr[n] = ss[255];
        return;
    }

    // ---- u/v GEMM branch
    int bi0  = blockIdx.x - 1;
    int half_ = bi0 >= gm ? 1 : 0;
    int bi   = bi0 - half_*gm;
    int m0   = bi * 128;
    int wid  = tid >> 5, lane = tid & 31;
    int wm   = (wid >> 1) * 32;
    int wn   = (wid & 1) * 64;
    int grp  = lane >> 2, qid = lane & 3;

    int arow  = (lane & 7) + ((lane >> 3) & 1) * 8;
    int aksel = (lane >> 4) * 8;
    int brow  = (lane & 7) + ((lane >> 4) ? 8 : 0);
    int bksel = ((lane >> 3) & 1) * 8;

    uint32_t bars[2] = { s2u(&barsto[0]), s2u(&barsto[1]) };
    if (tid == 0){ mbar_init(bars[0], 1); mbar_init(bars[1], 1); }
    __syncthreads();

    float acc[2][8][4];
    #pragma unroll
    for (int mt = 0; mt < 2; mt++)
        #pragma unroll
        for (int nt = 0; nt < 8; nt++)
            #pragma unroll
            for (int q = 0; q < 4; q++) acc[mt][nt][q] = 0.f;

    auto issue = [&](int t){
        int buf = t & 1;
        mbar_expect_tx(bars[buf], 2*BLKB);
        bulk_g2s(s2u(&st[buf][0]),    g_xb + ((size_t)bi*4 + t)*BLKH,      BLKB, bars[buf]);
        bulk_g2s(s2u(&st[buf][BLKH]), g_wuvb + ((size_t)half_*4 + t)*BLKH, BLKB, bars[buf]);
    };

    const int T = 4;
    if (tid == 0){ issue(0); issue(1); }

    for (int t = 0; t < T; t++){
        int cur = t & 1;
        mbar_wait(bars[cur], (t >> 1) & 1);
        const __half* A = &st[cur][0];
        const __half* W = &st[cur][BLKH];
        #pragma unroll
        for (int ks = 0; ks < 2; ks++){
            int kk = ks*16;
            uint32_t a[2][4], b[8][2];
            #pragma unroll
            for (int mt = 0; mt < 2; mt++){
                uint32_t addr = s2u(&A[(wm + mt*16 + arow)*PITCH + kk + aksel]);
                LDSM_X4(a[mt][0], a[mt][1], a[mt][2], a[mt][3], addr);
            }
            #pragma unroll
            for (int p = 0; p < 4; p++){
                uint32_t addr = s2u(&W[(wn + p*16 + brow)*PITCH + kk + bksel]);
                LDSM_X4(b[2*p][0], b[2*p][1], b[2*p+1][0], b[2*p+1][1], addr);
            }
            #pragma unroll
            for (int mt = 0; mt < 2; mt++)
                #pragma unroll
                for (int nt = 0; nt < 8; nt++)
                    MMA_F16(acc[mt][nt], a[mt][0],a[mt][1],a[mt][2],a[mt][3],
                            b[nt][0], b[nt][1]);
        }
        __syncthreads();
        if (t + 2 < T && tid == 0) issue(t + 2);
    }

    #pragma unroll
    for (int mt = 0; mt < 2; mt++){
        int row0 = m0 + wm + mt*16 + grp;
        #pragma unroll
        for (int nt = 0; nt < 8; nt++){
            int col = wn + nt*8 + 2*qid;
            if (half_){
                if (row0 < M)
                    *(__half2*)(g_vh + (size_t)row0*128 + col) =
                        __floats2half2_rn(acc[mt][nt][0], acc[mt][nt][1]);
                if (row0 + 8 < M)
                    *(__half2*)(g_vh + (size_t)(row0+8)*128 + col) =
                        __floats2half2_rn(acc[mt][nt][2], acc[mt][nt][3]);
            } else {
                float b0 = b_pre[col], b1 = b_pre[col+1];
                if (row0 < M)
                    *(float2*)(g_u + (size_t)row0*128 + col) =
                        make_float2(acc[mt][nt][0] + b0, acc[mt][nt][1] + b1);
                if (row0 + 8 < M)
                    *(float2*)(g_u + (size_t)(row0+8)*128 + col) =
                        make_float2(acc[mt][nt][2] + b0, acc[mt][nt][3] + b1);
            }
        }
    }
}

// ---------------- K3: scatter (blocks < SB) || combine (blocks >= SB) --------
// combine: 2 columns per 256-thread block; block SB+832 computes bias
__global__ void k3_scatter_combine(const int* __restrict__ src,
                                   const int* __restrict__ dst, int E, int SB,
                                   const float* __restrict__ W_post,
                                   const float* __restrict__ b_post,
                                   const float* __restrict__ b_lin){
    int b = blockIdx.x;
    if (b < SB){
        int e = b*256 + threadIdx.x;
        if (e < E){
            int d = dst[e];
            int p = atomicAdd(&g_cursor[d], 1);
            g_srcs[p] = src[e];
        }
        return;
    }
    int cb = b - SB;
    int f = threadIdx.x & 127;
    int half = threadIdx.x >> 7;
    if (cb == 832){
        if (threadIdx.x < 128){
            float s = b_lin[f];
            #pragma unroll 8
            for (int k = 0; k < FDIM; k++)
                s = fmaf(g_Wt_lin[k*FDIM + f], b_post[k], s);
            g_b_comb[f] = s;
        }
        return;
    }
    int c = cb*2 + half;
    __shared__ float col[2][FDIM];
    col[half][f] = W_post[(size_t)f*KPOST + c];
    __syncthreads();
    float s = 0.f;
    #pragma unroll 8
    for (int k = 0; k < FDIM; k++)
        s = fmaf(g_Wt_lin[k*FDIM + f], col[half][k], s);
    g_wcb[(size_t)(c >> 5)*BLKH + f*PITCH + (c & 31)] = __float2half_rn(s);
}

// ---------------- per-node aggregation (factored u, fp16 v gathers) ----------
__global__ void k_agg(int n){
    int node = blockIdx.x*2 + (threadIdx.x >> 6);
    int t = threadIdx.x & 63;
    if (node >= n) return;
    int s0 = g_rowptr[node], s1 = g_rowptr[node+1];
    const __half2* vh = (const __half2*)g_vh;

    __half2 hmx = __half2half2(__ushort_as_half((unsigned short)0xFC00));  // -inf
    __half2 hmn = __half2half2(__ushort_as_half((unsigned short)0x7C00));  // +inf
    float smx = 0.f, smy = 0.f, sqx = 0.f, sqy = 0.f;

    int e = s0;
    for (; e + 3 < s1; e += 4){
        int i0 = g_srcs[e], i1 = g_srcs[e+1], i2 = g_srcs[e+2], i3 = g_srcs[e+3];
        __half2 v0 = vh[(size_t)i0*64 + t];
        __half2 v1 = vh[(size_t)i1*64 + t];
        __half2 v2 = vh[(size_t)i2*64 + t];
        __half2 v3 = vh[(size_t)i3*64 + t];
        hmx = __hmax2(hmx, __hmax2(__hmax2(v0, v1), __hmax2(v2, v3)));
        hmn = __hmin2(hmn, __hmin2(__hmin2(v0, v1), __hmin2(v2, v3)));
        float2 f0 = __half22float2(v0), f1 = __half22float2(v1);
        float2 f2 = __half22float2(v2), f3 = __half22float2(v3);
        smx += f0.x + f1.x + f2.x + f3.x;
        smy += f0.y + f1.y + f2.y + f3.y;
        sqx = fmaf(f0.x, f0.x, sqx); sqx = fmaf(f1.x, f1.x, sqx);
        sqx = fmaf(f2.x, f2.x, sqx); sqx = fmaf(f3.x, f3.x, sqx);
        sqy = fmaf(f0.y, f0.y, sqy); sqy = fmaf(f1.y, f1.y, sqy);
        sqy = fmaf(f3.y, f3.y, sqy); sqy = fmaf(f2.y, f2.y, sqy);
    }
    for (; e < s1; e++){
        int s = g_srcs[e];
        __half2 v = vh[(size_t)s*64 + t];
        hmx = __hmax2(hmx, v);
        hmn = __hmin2(hmn, v);
        float2 f = __half22float2(v);
        smx += f.x; smy += f.y;
        sqx = fmaf(f.x, f.x, sqx);
        sqy = fmaf(f.y, f.y, sqy);
    }

    int deg = s1 - s0;
    float dc = fmaxf((float)deg, 1.f);
    float inv = 1.f / dc;
    float2 uf = *(const float2*)(g_u + (size_t)node*128 + 2*t);

    float vmx_x = __half2float(__low2half(hmx)),  vmx_y = __half2float(__high2half(hmx));
    float vmn_x = __half2float(__low2half(hmn)),  vmn_y = __half2float(__high2half(hmn));
    float vme_x = smx*inv, vme_y = smy*inv;

    float outv[4][2];
    outv[0][0] = deg ? (uf.x + vmx_x) : 0.f;
    outv[0][1] = deg ? (uf.y + vmx_y) : 0.f;
    outv[1][0] = deg ? (uf.x + vmn_x) : 0.f;
    outv[1][1] = deg ? (uf.y + vmn_y) : 0.f;
    outv[2][0] = deg ? (uf.x + vme_x) : 0.f;
    outv[2][1] = deg ? (uf.y + vme_y) : 0.f;
    outv[3][0] = sqrtf(fmaxf(sqx*inv - vme_x*vme_x, 0.f) + 1e-5f);
    outv[3][1] = sqrtf(fmaxf(sqy*inv - vme_y*vme_y, 0.f) + 1e-5f);

    size_t base = (size_t)(node >> 7)*16*BLKH + (node & 127)*PITCH;
    int off = (2*t) & 31;
    int csub = t >> 4;
    #pragma unroll
    for (int a = 0; a < 4; a++){
        __half2 h = __floats2half2_rn(outv[a][0], outv[a][1]);
        *(__half2*)(g_aggb + base + (size_t)(a*4 + csub)*BLKH + off) = h;
    }

    if (t == 0){
        float ld = logf(dc + 1.f);   // DELTA = 1.0
        g_amp[node] = ld;
        g_att[node] = 1.f / ld;
    }
}

// ---------------- factored FP16 post GEMM (bulk-copy pipelined) --------------
#define P_STAGE (4*BLKH)
#define POST_SMEM_BYTES (2*P_STAGE*2)

__global__ void __launch_bounds__(256, 1)
k_post3(int M, float* __restrict__ C)
{
    extern __shared__ __align__(16) __half smh[];
    __shared__ __align__(16) uint64_t barsto[2];

    int tid  = threadIdx.x;
    int bi   = blockIdx.x;
    int m0   = bi * 128;
    int wid  = tid >> 5, lane = tid & 31;
    int wm   = (wid >> 1) * 32;
    int wn   = (wid & 1) * 64;
    int grp  = lane >> 2, qid = lane & 3;

    int arow  = (lane & 7) + ((lane >> 3) & 1) * 8;
    int aksel = (lane >> 4) * 8;
    int brow  = (lane & 7) + ((lane >> 4) ? 8 : 0);
    int bksel = ((lane >> 3) & 1) * 8;

    uint32_t bars[2] = { s2u(&barsto[0]), s2u(&barsto[1]) };
    if (tid == 0){ mbar_init(bars[0], 1); mbar_init(bars[1], 1); }
    __syncthreads();

    float accC[2][8][4], accA[2][8][4], accT[2][8][4];
    #pragma unroll
    for (int mt = 0; mt < 2; mt++)
        #pragma unroll
        for (int nt = 0; nt < 8; nt++)
            #pragma unroll
            for (int q = 0; q < 4; q++){
                accC[mt][nt][q] = 0.f; accA[mt][nt][q] = 0.f; accT[mt][nt][q] = 0.f;
            }

    auto issue = [&](int t){
        int buf = t & 1;
        uint32_t sA  = s2u(&smh[buf*P_STAGE]);
        if (t < 4){
            mbar_expect_tx(bars[buf], 2*BLKB);
            bulk_g2s(sA,        g_xb + ((size_t)bi*4 + t)*BLKH, BLKB, bars[buf]);
            bulk_g2s(sA + BLKB, g_wcb + (size_t)t*BLKH,         BLKB, bars[buf]);
        } else {
            int ka = t - 4;
            mbar_expect_tx(bars[buf], 4*BLKB);
            bulk_g2s(sA,          g_aggb + ((size_t)bi*16 + ka)*BLKH, BLKB, bars[buf]);
            bulk_g2s(sA + 1*BLKB, g_wcb + (size_t)(4  + ka)*BLKH,     BLKB, bars[buf]);
            bulk_g2s(sA + 2*BLKB, g_wcb + (size_t)(20 + ka)*BLKH,     BLKB, bars[buf]);
            bulk_g2s(sA + 3*BLKB, g_wcb + (size_t)(36 + ka)*BLKH,     BLKB, bars[buf]);
        }
    };

    const int T = 20;
    if (tid == 0){ issue(0); issue(1); }

    for (int t = 0; t < T; t++){
        int cur = t & 1;
        mbar_wait(bars[cur], (t >> 1) & 1);
        const __half* S = &smh[cur*P_STAGE];
        int nsets = (t < 4) ? 1 : 3;
        #pragma unroll
        for (int ks = 0; ks < 2; ks++){
            int kk = ks*16;
            uint32_t a[2][4];
            #pragma unroll
            for (int mt = 0; mt < 2; mt++){
                uint32_t addr = s2u(&S[(wm + mt*16 + arow)*PITCH + kk + aksel]);
                LDSM_X4(a[mt][0], a[mt][1], a[mt][2], a[mt][3], addr);
            }
            #pragma unroll
            for (int s = 0; s < 3; s++){
                if (s >= nsets) break;
                const __half* W = S + (1 + s)*BLKH;
                uint32_t b[8][2];
                #pragma unroll
                for (int p = 0; p < 4; p++){
                    uint32_t addr = s2u(&W[(wn + p*16 + brow)*PITCH + kk + bksel]);
                    LDSM_X4(b[2*p][0], b[2*p][1], b[2*p+1][0], b[2*p+1][1], addr);
                }
                float (*acc)[8][4] = (s == 0) ? accC : (s == 1) ? accA : accT;
                #pragma unroll
                for (int mt = 0; mt < 2; mt++)
                    #pragma unroll
                    for (int nt = 0; nt < 8; nt++)
                        MMA_F16(acc[mt][nt], a[mt][0],a[mt][1],a[mt][2],a[mt][3],
                                b[nt][0], b[nt][1]);
            }
        }
        __syncthreads();
        if (t + 2 < T && tid == 0) issue(t + 2);
    }

    #pragma unroll
    for (int mt = 0; mt < 2; mt++){
        int row0 = m0 + wm + mt*16 + grp;
        int row1 = row0 + 8;
        float amp0 = 0.f, att0 = 0.f, amp1 = 0.f, att1 = 0.f;
        if (row0 < M){ amp0 = g_amp[row0]; att0 = g_att[row0]; }
        if (row1 < M){ amp1 = g_amp[row1]; att1 = g_att[row1]; }
        #pragma unroll
        for (int nt = 0; nt < 8; nt++){
            int col = wn + nt*8 + 2*qid;
            float b0 = g_b_comb[col], b1 = g_b_comb[col+1];
            if (row0 < M){
                float2 v;
                v.x = accC[mt][nt][0] + amp0*accA[mt][nt][0] + att0*accT[mt][nt][0] + b0;
                v.y = accC[mt][nt][1] + amp0*accA[mt][nt][1] + att0*accT[mt][nt][1] + b1;
                *(float2*)(C + (size_t)row0*128 + col) = v;
            }
            if (row1 < M){
                float2 v;
                v.x = accC[mt][nt][2] + amp1*accA[mt][nt][2] + att1*accT[mt][nt][2] + b0;
                v.y = accC[mt][nt][3] + amp1*accA[mt][nt][3] + att1*accT[mt][nt][3] + b1;
                *(float2*)(C + (size_t)row1*128 + col) = v;
            }
        }
    }
}

// ---------------- launch -----------------------------------------------------
extern "C" void kernel_launch(void* const* d_in, const int* in_sizes, int n_in,
                              void* d_out, int out_size)
{
    const float* x      = (const float*)d_in[0];
    const int*   ei     = (const int*)  d_in[1];
    const float* W_pre  = (const float*)d_in[2];
    const float* b_pre  = (const float*)d_in[3];
    const float* W_post = (const float*)d_in[4];
    const float* b_post = (const float*)d_in[5];
    const float* W_lin  = (const float*)d_in[6];
    const float* b_lin  = (const float*)d_in[7];
    float* out = (float*)d_out;

    int N = in_sizes[0] / FDIM;
    int E = in_sizes[1] / 2;
    const int* src = ei;        // edge_index[0] = x_j (source)
    const int* dst = ei + E;    // edge_index[1] = x_i (destination)

    cudaFuncSetAttribute(k_post3,
                         cudaFuncAttributeMaxDynamicSharedMemorySize, POST_SMEM_BYTES);

    int HB = (E + 255)/256;
    int gm = (N + 127)/128;

    // K1: hist || prep (blocked layouts + Wt_lin)
    k1_hist_prep<<<HB + PREP_BLOCKS, 256>>>(dst, E, HB, x, W_pre, W_lin, N);

    // K2: scan (block 0, also re-zeroes g_deg) || u/v fp16 GEMM
    k2_scan_uv<<<1 + 2*gm, 256>>>(N, N, gm, b_pre);

    // K3: scatter || combine (+bias)
    k3_scatter_combine<<<HB + 833, 256>>>(src, dst, E, HB, W_post, b_post, b_lin);

    // aggregation (fp16 gathers, blocked agg out)
    k_agg<<<(N+1)/2, 128>>>(N);

    // factored fp16 post GEMM (bulk pipelined)
    k_post3<<<gm, 256, POST_SMEM_BYTES>>>(N, out);
}

// round 13
// speedup vs baseline: 1.0213x; 1.0213x over previous
#include <cuda_runtime.h>
#include <cuda_fp16.h>
#include <math.h>
#include <stdint.h>

#define FDIM 128
#define NMAX 50000
#define EMAX 800000
#define KPOST (13*FDIM)   /* 1664 */
#define NT    ((NMAX + 127)/128)   /* 391 m-tiles */
#define PITCH 40                   /* halves per smem/blocked row */
#define BLKH  (128*PITCH)          /* halves per block: 5120 */
#define BLKB  (BLKH*2)             /* bytes per block: 10240 */

// ---------------- scratch (static device globals; no allocation) -------------
__device__ __align__(16) int    g_deg[NMAX];                      // stays zeroed between runs
__device__ __align__(16) int    g_rowptr[NMAX+1];
__device__ __align__(16) int    g_cursor[NMAX];
__device__ __align__(16) int    g_srcs[EMAX];
__device__ __align__(16) float  g_u[(size_t)NMAX*FDIM];
__device__ __align__(16) __half g_vh[(size_t)NMAX*FDIM];          // fp16 v (row-major)
__device__ __align__(16) __half g_xb[(size_t)NT*4*BLKH];          // x, chunk-blocked
__device__ __align__(16) __half g_aggb[(size_t)NT*16*BLKH];       // agg, chunk-blocked
__device__ __align__(16) float  g_amp[NMAX];
__device__ __align__(16) float  g_att[NMAX];
__device__ __align__(16) __half g_wuvb[2*4*BLKH];                 // W_uv, blocked
__device__ __align__(16) float  g_Wt_lin[FDIM*FDIM];              // [128][128] (k-major)
__device__ __align__(16) __half g_wcb[52*BLKH];                   // W_comb, blocked
__device__ __align__(16) float  g_b_comb[FDIM];

__device__ __forceinline__ uint32_t s2u(const void* p){
    return (uint32_t)__cvta_generic_to_shared(p);
}

// ---- cp.async.bulk (non-tensor) + mbarrier ----------------------------------
__device__ __forceinline__ void bulk_g2s(uint32_t dst, const void* src,
                                         uint32_t bytes, uint32_t mbar){
    uint64_t g;
    asm("cvta.to.global.u64 %0, %1;" : "=l"(g) : "l"(src));
    asm volatile(
        "cp.async.bulk.shared::cta.global.mbarrier::complete_tx::bytes "
        "[%0], [%1], %2, [%3];"
        :: "r"(dst), "l"(g), "r"(bytes), "r"(mbar) : "memory");
}
__device__ __forceinline__ void mbar_init(uint32_t mbar, uint32_t cnt){
    asm volatile("mbarrier.init.shared.b64 [%0], %1;" :: "r"(mbar), "r"(cnt) : "memory");
}
__device__ __forceinline__ void mbar_expect_tx(uint32_t mbar, uint32_t bytes){
    asm volatile("mbarrier.arrive.expect_tx.shared.b64 _, [%0], %1;"
                 :: "r"(mbar), "r"(bytes) : "memory");
}
__device__ __forceinline__ void mbar_wait(uint32_t mbar, uint32_t parity){
    uint32_t done = 0;
    while (!done){
        asm volatile(
            "{\n\t"
            ".reg .pred p;\n\t"
            "mbarrier.try_wait.parity.acquire.cta.shared::cta.b64 p, [%1], %2, 0x989680;\n\t"
            "selp.b32 %0, 1, 0, p;\n\t"
            "}"
            : "=r"(done) : "r"(mbar), "r"(parity) : "memory");
    }
}

#define MMA_F16(acc, a0,a1,a2,a3, b0,b1) \
    asm volatile( \
        "mma.sync.aligned.m16n8k16.row.col.f32.f16.f16.f32 " \
        "{%0,%1,%2,%3}, {%4,%5,%6,%7}, {%8,%9}, {%0,%1,%2,%3};\n" \
        : "+f"((acc)[0]), "+f"((acc)[1]), "+f"((acc)[2]), "+f"((acc)[3]) \
        : "r"(a0), "r"(a1), "r"(a2), "r"(a3), "r"(b0), "r"(b1))

#define LDSM_X4(r0,r1,r2,r3,addr) \
    asm volatile("ldmatrix.sync.aligned.m8n8.x4.shared.b16 {%0,%1,%2,%3}, [%4];" \
        : "=r"(r0), "=r"(r1), "=r"(r2), "=r"(r3) : "r"(addr))

// ---------------- CSR build --------------------------------------------------
__global__ void k_hist(const int* __restrict__ dst, int E){
    int e = blockIdx.x*blockDim.x + threadIdx.x;
    if (e < E) atomicAdd(&g_deg[dst[e]], 1);
}

// scan also re-zeroes g_deg for the next graph replay
__global__ void k_scan(int n){
    __shared__ int ss[1024];
    int t = threadIdx.x;
    int chunk = (n + 1023) >> 10;
    int lo = t*chunk;
    int hi = min(lo + chunk, n);
    int s = 0;
    for (int i = lo; i < hi; i++) s += g_deg[i];
    ss[t] = s;
    __syncthreads();
    for (int off = 1; off < 1024; off <<= 1){
        int v = (t >= off) ? ss[t-off] : 0;
        __syncthreads();
        ss[t] += v;
        __syncthreads();
    }
    int run = (t == 0) ? 0 : ss[t-1];
    for (int i = lo; i < hi; i++){
        g_rowptr[i] = run;
        g_cursor[i] = run;
        run += g_deg[i];
        g_deg[i] = 0;
    }
    if (t == 1023) g_rowptr[n] = ss[1023];
}

__global__ void k_scatter(const int* __restrict__ src, const int* __restrict__ dst, int E){
    int e = blockIdx.x*blockDim.x + threadIdx.x;
    if (e < E){
        int d = dst[e];
        int p = atomicAdd(&g_cursor[d], 1);
        g_srcs[p] = src[e];
    }
}

// ---------------- merged prep: blocked x + blocked Wuv + lin-transpose -------
__global__ void k_prep(const float* __restrict__ x, const float* __restrict__ W_pre,
                       const float* __restrict__ W_lin, int N){
    int stride = gridDim.x*blockDim.x;
    int i0 = blockIdx.x*blockDim.x + threadIdx.x;
    for (int i = i0; i < N*FDIM; i += stride){
        int node = i >> 7, col = i & 127;
        g_xb[((size_t)(node >> 7)*4 + (col >> 5))*BLKH + (node & 127)*PITCH + (col & 31)]
            = __float2half_rn(x[i]);
    }
    for (int i = i0; i < 256*128; i += stride){
        int j = i >> 7, k = i & 127;
        float val = W_pre[(size_t)(j & 127)*256 + ((j >> 7) ? (128 + k) : k)];
        g_wuvb[((size_t)(j >> 7)*4 + (k >> 5))*BLKH + (j & 127)*PITCH + (k & 31)]
            = __float2half_rn(val);
    }
    for (int i = i0; i < FDIM*FDIM; i += stride){
        int f = i >> 7, c = i & 127;
        g_Wt_lin[c*FDIM + f] = W_lin[i];
    }
}

// blocked W_comb: g_wcb[chunk=c>>5][f][c&31]; block KPOST computes bias
__global__ void k_combine(const float* __restrict__ W_post,
                          const float* __restrict__ b_post,
                          const float* __restrict__ b_lin){
    int f = threadIdx.x;
    if (blockIdx.x == KPOST){
        float s = b_lin[f];
        #pragma unroll 8
        for (int k = 0; k < FDIM; k++)
            s = fmaf(g_Wt_lin[k*FDIM + f], b_post[k], s);
        g_b_comb[f] = s;
        return;
    }
    int c = blockIdx.x;
    __shared__ float col[FDIM];
    col[f] = W_post[(size_t)f*KPOST + c];
    __syncthreads();
    float s = 0.f;
    #pragma unroll 8
    for (int k = 0; k < FDIM; k++)
        s = fmaf(g_Wt_lin[k*FDIM + f], col[k], s);
    g_wcb[(size_t)(c >> 5)*BLKH + f*PITCH + (c & 31)] = __float2half_rn(s);
}

// ---------------- u/v FP16 GEMM: bulk-copy pipelined (K=128) -----------------
// gridDim.y: 0 -> u (fp32 + bias), 1 -> v (fp16, no bias)
__global__ void __launch_bounds__(256, 2)
k_uv_f16(int M, const float* __restrict__ b_pre)
{
    __shared__ __align__(16) __half st[2][2*BLKH];   // [stage][A | W]
    __shared__ __align__(16) uint64_t barsto[2];

    int tid  = threadIdx.x;
    int bi   = blockIdx.x;
    int m0   = bi * 128;
    int half_ = blockIdx.y;
    int wid  = tid >> 5, lane = tid & 31;
    int wm   = (wid >> 1) * 32;
    int wn   = (wid & 1) * 64;
    int grp  = lane >> 2, qid = lane & 3;

    int arow  = (lane & 7) + ((lane >> 3) & 1) * 8;
    int aksel = (lane >> 4) * 8;
    int brow  = (lane & 7) + ((lane >> 4) ? 8 : 0);
    int bksel = ((lane >> 3) & 1) * 8;

    uint32_t bars[2] = { s2u(&barsto[0]), s2u(&barsto[1]) };
    if (tid == 0){ mbar_init(bars[0], 1); mbar_init(bars[1], 1); }
    __syncthreads();

    float acc[2][8][4];
    #pragma unroll
    for (int mt = 0; mt < 2; mt++)
        #pragma unroll
        for (int nt = 0; nt < 8; nt++)
            #pragma unroll
            for (int q = 0; q < 4; q++) acc[mt][nt][q] = 0.f;

    auto issue = [&](int t){
        int buf = t & 1;
        mbar_expect_tx(bars[buf], 2*BLKB);
        bulk_g2s(s2u(&st[buf][0]),    g_xb + ((size_t)bi*4 + t)*BLKH,      BLKB, bars[buf]);
        bulk_g2s(s2u(&st[buf][BLKH]), g_wuvb + ((size_t)half_*4 + t)*BLKH, BLKB, bars[buf]);
    };

    const int T = 4;
    if (tid == 0){ issue(0); issue(1); }

    for (int t = 0; t < T; t++){
        int cur = t & 1;
        mbar_wait(bars[cur], (t >> 1) & 1);
        const __half* A = &st[cur][0];
        const __half* W = &st[cur][BLKH];
        #pragma unroll
        for (int ks = 0; ks < 2; ks++){
            int kk = ks*16;
            uint32_t a[2][4], b[8][2];
            #pragma unroll
            for (int mt = 0; mt < 2; mt++){
                uint32_t addr = s2u(&A[(wm + mt*16 + arow)*PITCH + kk + aksel]);
                LDSM_X4(a[mt][0], a[mt][1], a[mt][2], a[mt][3], addr);
            }
            #pragma unroll
            for (int p = 0; p < 4; p++){
                uint32_t addr = s2u(&W[(wn + p*16 + brow)*PITCH + kk + bksel]);
                LDSM_X4(b[2*p][0], b[2*p][1], b[2*p+1][0], b[2*p+1][1], addr);
            }
            #pragma unroll
            for (int mt = 0; mt < 2; mt++)
                #pragma unroll
                for (int nt = 0; nt < 8; nt++)
                    MMA_F16(acc[mt][nt], a[mt][0],a[mt][1],a[mt][2],a[mt][3],
                            b[nt][0], b[nt][1]);
        }
        __syncthreads();
        if (t + 2 < T && tid == 0) issue(t + 2);
    }

    #pragma unroll
    for (int mt = 0; mt < 2; mt++){
        int row0 = m0 + wm + mt*16 + grp;
        #pragma unroll
        for (int nt = 0; nt < 8; nt++){
            int col = wn + nt*8 + 2*qid;
            if (half_){
                if (row0 < M)
                    *(__half2*)(g_vh + (size_t)row0*128 + col) =
                        __floats2half2_rn(acc[mt][nt][0], acc[mt][nt][1]);
                if (row0 + 8 < M)
                    *(__half2*)(g_vh + (size_t)(row0+8)*128 + col) =
                        __floats2half2_rn(acc[mt][nt][2], acc[mt][nt][3]);
            } else {
                float b0 = b_pre[col], b1 = b_pre[col+1];
                if (row0 < M)
                    *(float2*)(g_u + (size_t)row0*128 + col) =
                        make_float2(acc[mt][nt][0] + b0, acc[mt][nt][1] + b1);
                if (row0 + 8 < M)
                    *(float2*)(g_u + (size_t)(row0+8)*128 + col) =
                        make_float2(acc[mt][nt][2] + b0, acc[mt][nt][3] + b1);
            }
        }
    }
}

// ---------------- per-node aggregation (factored u, fp16 v gathers) ----------
// int4 loads of g_srcs (alignment prologue); 2 nodes / 128-thread block
__global__ void k_agg(int n){
    int node = blockIdx.x*2 + (threadIdx.x >> 6);
    int t = threadIdx.x & 63;
    if (node >= n) return;
    int s0 = g_rowptr[node], s1 = g_rowptr[node+1];
    const __half2* vh = (const __half2*)g_vh;

    __half2 hmx = __half2half2(__ushort_as_half((unsigned short)0xFC00));  // -inf
    __half2 hmn = __half2half2(__ushort_as_half((unsigned short)0x7C00));  // +inf
    float smx = 0.f, smy = 0.f, sqx = 0.f, sqy = 0.f;

    int e = s0;
    // align e to 4 for int4 loads
    for (; e < s1 && (e & 3); e++){
        int s = g_srcs[e];
        __half2 v = vh[(size_t)s*64 + t];
        hmx = __hmax2(hmx, v);
        hmn = __hmin2(hmn, v);
        float2 f = __half22float2(v);
        smx += f.x; smy += f.y;
        sqx = fmaf(f.x, f.x, sqx);
        sqy = fmaf(f.y, f.y, sqy);
    }
    for (; e + 3 < s1; e += 4){
        int4 s4 = *(const int4*)(g_srcs + e);
        __half2 v0 = vh[(size_t)s4.x*64 + t];
        __half2 v1 = vh[(size_t)s4.y*64 + t];
        __half2 v2 = vh[(size_t)s4.z*64 + t];
        __half2 v3 = vh[(size_t)s4.w*64 + t];
        hmx = __hmax2(hmx, __hmax2(__hmax2(v0, v1), __hmax2(v2, v3)));
        hmn = __hmin2(hmn, __hmin2(__hmin2(v0, v1), __hmin2(v2, v3)));
        float2 f0 = __half22float2(v0), f1 = __half22float2(v1);
        float2 f2 = __half22float2(v2), f3 = __half22float2(v3);
        smx += f0.x + f1.x + f2.x + f3.x;
        smy += f0.y + f1.y + f2.y + f3.y;
        sqx = fmaf(f0.x, f0.x, sqx); sqx = fmaf(f1.x, f1.x, sqx);
        sqx = fmaf(f2.x, f2.x, sqx); sqx = fmaf(f3.x, f3.x, sqx);
        sqy = fmaf(f0.y, f0.y, sqy); sqy = fmaf(f1.y, f1.y, sqy);
        sqy = fmaf(f2.y, f2.y, sqy); sqy = fmaf(f3.y, f3.y, sqy);
    }
    for (; e < s1; e++){
        int s = g_srcs[e];
        __half2 v = vh[(size_t)s*64 + t];
        hmx = __hmax2(hmx, v);
        hmn = __hmin2(hmn, v);
        float2 f = __half22float2(v);
        smx += f.x; smy += f.y;
        sqx = fmaf(f.x, f.x, sqx);
        sqy = fmaf(f.y, f.y, sqy);
    }

    int deg = s1 - s0;
    float dc = fmaxf((float)deg, 1.f);
    float inv = 1.f / dc;
    float2 uf = *(const float2*)(g_u + (size_t)node*128 + 2*t);

    float vmx_x = __half2float(__low2half(hmx)),  vmx_y = __half2float(__high2half(hmx));
    float vmn_x = __half2float(__low2half(hmn)),  vmn_y = __half2float(__high2half(hmn));
    float vme_x = smx*inv, vme_y = smy*inv;

    float outv[4][2];
    outv[0][0] = deg ? (uf.x + vmx_x) : 0.f;
    outv[0][1] = deg ? (uf.y + vmx_y) : 0.f;
    outv[1][0] = deg ? (uf.x + vmn_x) : 0.f;
    outv[1][1] = deg ? (uf.y + vmn_y) : 0.f;
    outv[2][0] = deg ? (uf.x + vme_x) : 0.f;
    outv[2][1] = deg ? (uf.y + vme_y) : 0.f;
    outv[3][0] = sqrtf(fmaxf(sqx*inv - vme_x*vme_x, 0.f) + 1e-5f);
    outv[3][1] = sqrtf(fmaxf(sqy*inv - vme_y*vme_y, 0.f) + 1e-5f);

    // blocked write: agg col c = a*128 + 2t -> chunk = a*4 + (t>>4), off = (2t)&31
    size_t base = (size_t)(node >> 7)*16*BLKH + (node & 127)*PITCH;
    int off = (2*t) & 31;
    int csub = t >> 4;
    #pragma unroll
    for (int a = 0; a < 4; a++){
        __half2 h = __floats2half2_rn(outv[a][0], outv[a][1]);
        *(__half2*)(g_aggb + base + (size_t)(a*4 + csub)*BLKH + off) = h;
    }

    if (t == 0){
        float ld = logf(dc + 1.f);   // DELTA = 1.0
        g_amp[node] = ld;
        g_att[node] = 1.f / ld;
    }
}

// ---------------- factored FP16 post GEMM (bulk-copy pipelined) --------------
#define P_STAGE (4*BLKH)
#define POST_SMEM_BYTES (2*P_STAGE*2)

__global__ void __launch_bounds__(256, 1)
k_post3(int M, float* __restrict__ C)
{
    extern __shared__ __align__(16) __half smh[];
    __shared__ __align__(16) uint64_t barsto[2];

    int tid  = threadIdx.x;
    int bi   = blockIdx.x;
    int m0   = bi * 128;
    int wid  = tid >> 5, lane = tid & 31;
    int wm   = (wid >> 1) * 32;
    int wn   = (wid & 1) * 64;
    int grp  = lane >> 2, qid = lane & 3;

    int arow  = (lane & 7) + ((lane >> 3) & 1) * 8;
    int aksel = (lane >> 4) * 8;
    int brow  = (lane & 7) + ((lane >> 4) ? 8 : 0);
    int bksel = ((lane >> 3) & 1) * 8;

    uint32_t bars[2] = { s2u(&barsto[0]), s2u(&barsto[1]) };
    if (tid == 0){ mbar_init(bars[0], 1); mbar_init(bars[1], 1); }
    __syncthreads();

    float accC[2][8][4], accA[2][8][4], accT[2][8][4];
    #pragma unroll
    for (int mt = 0; mt < 2; mt++)
        #pragma unroll
        for (int nt = 0; nt < 8; nt++)
            #pragma unroll
            for (int q = 0; q < 4; q++){
                accC[mt][nt][q] = 0.f; accA[mt][nt][q] = 0.f; accT[mt][nt][q] = 0.f;
            }

    auto issue = [&](int t){
        int buf = t & 1;
        uint32_t sA  = s2u(&smh[buf*P_STAGE]);
        if (t < 4){
            mbar_expect_tx(bars[buf], 2*BLKB);
            bulk_g2s(sA,        g_xb + ((size_t)bi*4 + t)*BLKH, BLKB, bars[buf]);
            bulk_g2s(sA + BLKB, g_wcb + (size_t)t*BLKH,         BLKB, bars[buf]);
        } else {
            int ka = t - 4;
            mbar_expect_tx(bars[buf], 4*BLKB);
            bulk_g2s(sA,          g_aggb + ((size_t)bi*16 + ka)*BLKH, BLKB, bars[buf]);
            bulk_g2s(sA + 1*BLKB, g_wcb + (size_t)(4  + ka)*BLKH,     BLKB, bars[buf]);
            bulk_g2s(sA + 2*BLKB, g_wcb + (size_t)(20 + ka)*BLKH,     BLKB, bars[buf]);
            bulk_g2s(sA + 3*BLKB, g_wcb + (size_t)(36 + ka)*BLKH,     BLKB, bars[buf]);
        }
    };

    const int T = 20;
    if (tid == 0){ issue(0); issue(1); }

    for (int t = 0; t < T; t++){
        int cur = t & 1;
        mbar_wait(bars[cur], (t >> 1) & 1);
        const __half* S = &smh[cur*P_STAGE];
        int nsets = (t < 4) ? 1 : 3;
        #pragma unroll
        for (int ks = 0; ks < 2; ks++){
            int kk = ks*16;
            uint32_t a[2][4];
            #pragma unroll
            for (int mt = 0; mt < 2; mt++){
                uint32_t addr = s2u(&S[(wm + mt*16 + arow)*PITCH + kk + aksel]);
                LDSM_X4(a[mt][0], a[mt][1], a[mt][2], a[mt][3], addr);
            }
            #pragma unroll
            for (int s = 0; s < 3; s++){
                if (s >= nsets) break;
                const __half* W = S + (1 + s)*BLKH;
                uint32_t b[8][2];
                #pragma unroll
                for (int p = 0; p < 4; p++){
                    uint32_t addr = s2u(&W[(wn + p*16 + brow)*PITCH + kk + bksel]);
                    LDSM_X4(b[2*p][0], b[2*p][1], b[2*p+1][0], b[2*p+1][1], addr);
                }
                float (*acc)[8][4] = (s == 0) ? accC : (s == 1) ? accA : accT;
                #pragma unroll
                for (int mt = 0; mt < 2; mt++)
                    #pragma unroll
                    for (int nt = 0; nt < 8; nt++)
                        MMA_F16(acc[mt][nt], a[mt][0],a[mt][1],a[mt][2],a[mt][3],
                                b[nt][0], b[nt][1]);
            }
        }
        __syncthreads();
        if (t + 2 < T && tid == 0) issue(t + 2);
    }

    #pragma unroll
    for (int mt = 0; mt < 2; mt++){
        int row0 = m0 + wm + mt*16 + grp;
        int row1 = row0 + 8;
        float amp0 = 0.f, att0 = 0.f, amp1 = 0.f, att1 = 0.f;
        if (row0 < M){ amp0 = g_amp[row0]; att0 = g_att[row0]; }
        if (row1 < M){ amp1 = g_amp[row1]; att1 = g_att[row1]; }
        #pragma unroll
        for (int nt = 0; nt < 8; nt++){
            int col = wn + nt*8 + 2*qid;
            float b0 = g_b_comb[col], b1 = g_b_comb[col+1];
            if (row0 < M){
                float2 v;
                v.x = accC[mt][nt][0] + amp0*accA[mt][nt][0] + att0*accT[mt][nt][0] + b0;
                v.y = accC[mt][nt][1] + amp0*accA[mt][nt][1] + att0*accT[mt][nt][1] + b1;
                *(float2*)(C + (size_t)row0*128 + col) = v;
            }
            if (row1 < M){
                float2 v;
                v.x = accC[mt][nt][2] + amp1*accA[mt][nt][2] + att1*accT[mt][nt][2] + b0;
                v.y = accC[mt][nt][3] + amp1*accA[mt][nt][3] + att1*accT[mt][nt][3] + b1;
                *(float2*)(C + (size_t)row1*128 + col) = v;
            }
        }
    }
}

// ---------------- launch -----------------------------------------------------
extern "C" void kernel_launch(void* const* d_in, const int* in_sizes, int n_in,
                              void* d_out, int out_size)
{
    const float* x      = (const float*)d_in[0];
    const int*   ei     = (const int*)  d_in[1];
    const float* W_pre  = (const float*)d_in[2];
    const float* b_pre  = (const float*)d_in[3];
    const float* W_post = (const float*)d_in[4];
    const float* b_post = (const float*)d_in[5];
    const float* W_lin  = (const float*)d_in[6];
    const float* b_lin  = (const float*)d_in[7];
    float* out = (float*)d_out;

    int N = in_sizes[0] / FDIM;
    int E = in_sizes[1] / 2;
    const int* src = ei;        // edge_index[0] = x_j (source)
    const int* dst = ei + E;    // edge_index[1] = x_i (destination)

    cudaFuncSetAttribute(k_post3,
                         cudaFuncAttributeMaxDynamicSharedMemorySize, POST_SMEM_BYTES);

    // CSR build (k_scan re-zeroes g_deg for next replay)
    k_hist   <<<(E+255)/256, 256>>>(dst, E);
    k_scan   <<<1, 1024>>>(N);
    k_scatter<<<(E+255)/256, 256>>>(src, dst, E);

    // merged prep (blocked layouts) + combined weights
    k_prep<<<(N*FDIM+255)/256, 256>>>(x, W_pre, W_lin, N);
    k_combine<<<KPOST+1, FDIM>>>(W_post, b_post, b_lin);

    // u/v fp16 GEMM (bulk pipelined)
    int gm = (N + 127)/128;
    dim3 guv(gm, 2);
    k_uv_f16<<<guv, 256>>>(N, b_pre);

    // factored aggregation (fp16 gathers, int4 srcs, blocked agg out)
    k_agg<<<(N+1)/2, 128>>>(N);

    // factored fp16 post GEMM (bulk pipelined)
    k_post3<<<gm, 256, POST_SMEM_BYTES>>>(N, out);
}

// round 14
// speedup vs baseline: 1.0847x; 1.0621x over previous
#include <cuda_runtime.h>
#include <cuda_fp16.h>
#include <math.h>
#include <stdint.h>

#define FDIM 128
#define NMAX 50000
#define EMAX 800000
#define KPOST (13*FDIM)   /* 1664 */
#define NT    ((NMAX + 127)/128)   /* 391 m-tiles */
#define PITCH 40                   /* halves per smem/blocked row */
#define BLKH  (128*PITCH)          /* halves per block: 5120 */
#define BLKB  (BLKH*2)             /* bytes per block: 10240 */

// ---------------- scratch (static device globals; no allocation) -------------
__device__ __align__(16) int    g_deg[NMAX];                      // stays zeroed between runs
__device__ __align__(16) int    g_rowptr[NMAX+1];
__device__ __align__(16) int    g_cursor[NMAX];
__device__ __align__(16) int    g_srcs[EMAX];
__device__ __align__(16) float  g_u[(size_t)NMAX*FDIM];
__device__ __align__(16) __half g_vh[(size_t)NMAX*FDIM];          // fp16 v (row-major)
__device__ __align__(16) __half g_xb[(size_t)NT*4*BLKH];          // x, chunk-blocked
__device__ __align__(16) __half g_aggb[(size_t)NT*16*BLKH];       // agg, chunk-blocked
__device__ __align__(16) float  g_amp[NMAX];
__device__ __align__(16) float  g_att[NMAX];
__device__ __align__(16) __half g_wuvb[2*4*BLKH];                 // W_uv, blocked
__device__ __align__(16) float  g_Wt_lin[FDIM*FDIM];              // [128][128] (k-major)
__device__ __align__(16) __half g_wcb[52*BLKH];                   // W_comb, blocked
__device__ __align__(16) float  g_b_comb[FDIM];

__device__ __forceinline__ uint32_t s2u(const void* p){
    return (uint32_t)__cvta_generic_to_shared(p);
}

// ---- cp.async.bulk (non-tensor) + mbarrier ----------------------------------
__device__ __forceinline__ void bulk_g2s(uint32_t dst, const void* src,
                                         uint32_t bytes, uint32_t mbar){
    uint64_t g;
    asm("cvta.to.global.u64 %0, %1;" : "=l"(g) : "l"(src));
    asm volatile(
        "cp.async.bulk.shared::cta.global.mbarrier::complete_tx::bytes "
        "[%0], [%1], %2, [%3];"
        :: "r"(dst), "l"(g), "r"(bytes), "r"(mbar) : "memory");
}
__device__ __forceinline__ void mbar_init(uint32_t mbar, uint32_t cnt){
    asm volatile("mbarrier.init.shared.b64 [%0], %1;" :: "r"(mbar), "r"(cnt) : "memory");
}
__device__ __forceinline__ void mbar_expect_tx(uint32_t mbar, uint32_t bytes){
    asm volatile("mbarrier.arrive.expect_tx.shared.b64 _, [%0], %1;"
                 :: "r"(mbar), "r"(bytes) : "memory");
}
__device__ __forceinline__ void mbar_wait(uint32_t mbar, uint32_t parity){
    uint32_t done = 0;
    while (!done){
        asm volatile(
            "{\n\t"
            ".reg .pred p;\n\t"
            "mbarrier.try_wait.parity.acquire.cta.shared::cta.b64 p, [%1], %2, 0x989680;\n\t"
            "selp.b32 %0, 1, 0, p;\n\t"
            "}"
            : "=r"(done) : "r"(mbar), "r"(parity) : "memory");
    }
}

#define MMA_F16(acc, a0,a1,a2,a3, b0,b1) \
    asm volatile( \
        "mma.sync.aligned.m16n8k16.row.col.f32.f16.f16.f32 " \
        "{%0,%1,%2,%3}, {%4,%5,%6,%7}, {%8,%9}, {%0,%1,%2,%3};\n" \
        : "+f"((acc)[0]), "+f"((acc)[1]), "+f"((acc)[2]), "+f"((acc)[3]) \
        : "r"(a0), "r"(a1), "r"(a2), "r"(a3), "r"(b0), "r"(b1))

#define LDSM_X4(r0,r1,r2,r3,addr) \
    asm volatile("ldmatrix.sync.aligned.m8n8.x4.shared.b16 {%0,%1,%2,%3}, [%4];" \
        : "=r"(r0), "=r"(r1), "=r"(r2), "=r"(r3) : "r"(addr))

// ---------------- CSR build --------------------------------------------------
__global__ void k_hist(const int* __restrict__ dst, int E){
    int e = blockIdx.x*blockDim.x + threadIdx.x;
    if (e < E) atomicAdd(&g_deg[dst[e]], 1);
}

// scan also re-zeroes g_deg for the next graph replay
__global__ void k_scan(int n){
    __shared__ int ss[1024];
    int t = threadIdx.x;
    int chunk = (n + 1023) >> 10;
    int lo = t*chunk;
    int hi = min(lo + chunk, n);
    int s = 0;
    for (int i = lo; i < hi; i++) s += g_deg[i];
    ss[t] = s;
    __syncthreads();
    for (int off = 1; off < 1024; off <<= 1){
        int v = (t >= off) ? ss[t-off] : 0;
        __syncthreads();
        ss[t] += v;
        __syncthreads();
    }
    int run = (t == 0) ? 0 : ss[t-1];
    for (int i = lo; i < hi; i++){
        g_rowptr[i] = run;
        g_cursor[i] = run;
        run += g_deg[i];
        g_deg[i] = 0;
    }
    if (t == 1023) g_rowptr[n] = ss[1023];
}

__global__ void k_scatter(const int* __restrict__ src, const int* __restrict__ dst, int E){
    int e = blockIdx.x*blockDim.x + threadIdx.x;
    if (e < E){
        int d = dst[e];
        int p = atomicAdd(&g_cursor[d], 1);
        g_srcs[p] = src[e];
    }
}

// ---------------- vectorized prep: blocked x + blocked Wuv + lin-transpose ---
__global__ void k_prep(const float* __restrict__ x, const float* __restrict__ W_pre,
                       const float* __restrict__ W_lin, int N){
    int stride = gridDim.x*blockDim.x;
    int i0 = blockIdx.x*blockDim.x + threadIdx.x;
    // x: 4 cols per item
    for (int i = i0; i < N*32; i += stride){
        int node = i >> 5, c4 = i & 31;
        float4 v = *(const float4*)(x + (size_t)node*128 + c4*4);
        size_t dst = ((size_t)(node >> 7)*4 + (c4 >> 3))*BLKH
                   + (size_t)(node & 127)*PITCH + (c4 & 7)*4;
        *(__half2*)(g_xb + dst)     = __floats2half2_rn(v.x, v.y);
        *(__half2*)(g_xb + dst + 2) = __floats2half2_rn(v.z, v.w);
    }
    // W_uv: 4 k per item
    for (int i = i0; i < 256*32; i += stride){
        int j = i >> 5, k4 = i & 31;
        float4 v = *(const float4*)(W_pre + (size_t)(j & 127)*256
                                    + ((j >> 7) ? 128 : 0) + k4*4);
        size_t dst = ((size_t)(j >> 7)*4 + (k4 >> 3))*BLKH
                   + (size_t)(j & 127)*PITCH + (k4 & 7)*4;
        *(__half2*)(g_wuvb + dst)     = __floats2half2_rn(v.x, v.y);
        *(__half2*)(g_wuvb + dst + 2) = __floats2half2_rn(v.z, v.w);
    }
    for (int i = i0; i < FDIM*FDIM; i += stride){
        int f = i >> 7, c = i & 127;
        g_Wt_lin[c*FDIM + f] = W_lin[i];
    }
}

// blocked W_comb: g_wcb[chunk=c>>5][f][c&31]; block KPOST computes bias
__global__ void k_combine(const float* __restrict__ W_post,
                          const float* __restrict__ b_post,
                          const float* __restrict__ b_lin){
    int f = threadIdx.x;
    if (blockIdx.x == KPOST){
        float s = b_lin[f];
        #pragma unroll 8
        for (int k = 0; k < FDIM; k++)
            s = fmaf(g_Wt_lin[k*FDIM + f], b_post[k], s);
        g_b_comb[f] = s;
        return;
    }
    int c = blockIdx.x;
    __shared__ float col[FDIM];
    col[f] = W_post[(size_t)f*KPOST + c];
    __syncthreads();
    float s = 0.f;
    #pragma unroll 8
    for (int k = 0; k < FDIM; k++)
        s = fmaf(g_Wt_lin[k*FDIM + f], col[k], s);
    g_wcb[(size_t)(c >> 5)*BLKH + f*PITCH + (c & 31)] = __float2half_rn(s);
}

// ---------------- u/v FP16 GEMM: bulk-copy pipelined (K=128) -----------------
// gridDim.y: 0 -> u (fp32 + bias), 1 -> v (fp16, no bias)
__global__ void __launch_bounds__(256, 2)
k_uv_f16(int M, const float* __restrict__ b_pre)
{
    __shared__ __align__(16) __half st[2][2*BLKH];   // [stage][A | W]
    __shared__ __align__(16) uint64_t barsto[2];

    int tid  = threadIdx.x;
    int bi   = blockIdx.x;
    int m0   = bi * 128;
    int half_ = blockIdx.y;
    int wid  = tid >> 5, lane = tid & 31;
    int wm   = (wid >> 1) * 32;
    int wn   = (wid & 1) * 64;
    int grp  = lane >> 2, qid = lane & 3;

    int arow  = (lane & 7) + ((lane >> 3) & 1) * 8;
    int aksel = (lane >> 4) * 8;
    int brow  = (lane & 7) + ((lane >> 4) ? 8 : 0);
    int bksel = ((lane >> 3) & 1) * 8;

    uint32_t bars[2] = { s2u(&barsto[0]), s2u(&barsto[1]) };
    if (tid == 0){ mbar_init(bars[0], 1); mbar_init(bars[1], 1); }
    __syncthreads();

    float acc[2][8][4];
    #pragma unroll
    for (int mt = 0; mt < 2; mt++)
        #pragma unroll
        for (int nt = 0; nt < 8; nt++)
            #pragma unroll
            for (int q = 0; q < 4; q++) acc[mt][nt][q] = 0.f;

    auto issue = [&](int t){
        int buf = t & 1;
        mbar_expect_tx(bars[buf], 2*BLKB);
        bulk_g2s(s2u(&st[buf][0]),    g_xb + ((size_t)bi*4 + t)*BLKH,      BLKB, bars[buf]);
        bulk_g2s(s2u(&st[buf][BLKH]), g_wuvb + ((size_t)half_*4 + t)*BLKH, BLKB, bars[buf]);
    };

    const int T = 4;
    if (tid == 0){ issue(0); issue(1); }

    for (int t = 0; t < T; t++){
        int cur = t & 1;
        mbar_wait(bars[cur], (t >> 1) & 1);
        const __half* A = &st[cur][0];
        const __half* W = &st[cur][BLKH];
        #pragma unroll
        for (int ks = 0; ks < 2; ks++){
            int kk = ks*16;
            uint32_t a[2][4], b[8][2];
            #pragma unroll
            for (int mt = 0; mt < 2; mt++){
                uint32_t addr = s2u(&A[(wm + mt*16 + arow)*PITCH + kk + aksel]);
                LDSM_X4(a[mt][0], a[mt][1], a[mt][2], a[mt][3], addr);
            }
            #pragma unroll
            for (int p = 0; p < 4; p++){
                uint32_t addr = s2u(&W[(wn + p*16 + brow)*PITCH + kk + bksel]);
                LDSM_X4(b[2*p][0], b[2*p][1], b[2*p+1][0], b[2*p+1][1], addr);
            }
            #pragma unroll
            for (int mt = 0; mt < 2; mt++)
                #pragma unroll
                for (int nt = 0; nt < 8; nt++)
                    MMA_F16(acc[mt][nt], a[mt][0],a[mt][1],a[mt][2],a[mt][3],
                            b[nt][0], b[nt][1]);
        }
        __syncthreads();
        if (t + 2 < T && tid == 0) issue(t + 2);
    }

    #pragma unroll
    for (int mt = 0; mt < 2; mt++){
        int row0 = m0 + wm + mt*16 + grp;
        #pragma unroll
        for (int nt = 0; nt < 8; nt++){
            int col = wn + nt*8 + 2*qid;
            if (half_){
                if (row0 < M)
                    *(__half2*)(g_vh + (size_t)row0*128 + col) =
                        __floats2half2_rn(acc[mt][nt][0], acc[mt][nt][1]);
                if (row0 + 8 < M)
                    *(__half2*)(g_vh + (size_t)(row0+8)*128 + col) =
                        __floats2half2_rn(acc[mt][nt][2], acc[mt][nt][3]);
            } else {
                float b0 = b_pre[col], b1 = b_pre[col+1];
                if (row0 < M)
                    *(float2*)(g_u + (size_t)row0*128 + col) =
                        make_float2(acc[mt][nt][0] + b0, acc[mt][nt][1] + b1);
                if (row0 + 8 < M)
                    *(float2*)(g_u + (size_t)(row0+8)*128 + col) =
                        make_float2(acc[mt][nt][2] + b0, acc[mt][nt][3] + b1);
            }
        }
    }
}

// ---------------- per-node aggregation (R11 version: factored u, fp16 gathers)
__global__ void k_agg(int n){
    int node = blockIdx.x*2 + (threadIdx.x >> 6);
    int t = threadIdx.x & 63;
    if (node >= n) return;
    int s0 = g_rowptr[node], s1 = g_rowptr[node+1];
    const __half2* vh = (const __half2*)g_vh;

    __half2 hmx = __half2half2(__ushort_as_half((unsigned short)0xFC00));  // -inf
    __half2 hmn = __half2half2(__ushort_as_half((unsigned short)0x7C00));  // +inf
    float smx = 0.f, smy = 0.f, sqx = 0.f, sqy = 0.f;

    int e = s0;
    for (; e + 3 < s1; e += 4){
        int i0 = g_srcs[e], i1 = g_srcs[e+1], i2 = g_srcs[e+2], i3 = g_srcs[e+3];
        __half2 v0 = vh[(size_t)i0*64 + t];
        __half2 v1 = vh[(size_t)i1*64 + t];
        __half2 v2 = vh[(size_t)i2*64 + t];
        __half2 v3 = vh[(size_t)i3*64 + t];
        hmx = __hmax2(hmx, __hmax2(__hmax2(v0, v1), __hmax2(v2, v3)));
        hmn = __hmin2(hmn, __hmin2(__hmin2(v0, v1), __hmin2(v2, v3)));
        float2 f0 = __half22float2(v0), f1 = __half22float2(v1);
        float2 f2 = __half22float2(v2), f3 = __half22float2(v3);
        smx += f0.x + f1.x + f2.x + f3.x;
        smy += f0.y + f1.y + f2.y + f3.y;
        sqx = fmaf(f0.x, f0.x, sqx); sqx = fmaf(f1.x, f1.x, sqx);
        sqx = fmaf(f2.x, f2.x, sqx); sqx = fmaf(f3.x, f3.x, sqx);
        sqy = fmaf(f0.y, f0.y, sqy); sqy = fmaf(f1.y, f1.y, sqy);
        sqy = fmaf(f2.y, f2.y, sqy); sqy = fmaf(f3.y, f3.y, sqy);
    }
    for (; e < s1; e++){
        int s = g_srcs[e];
        __half2 v = vh[(size_t)s*64 + t];
        hmx = __hmax2(hmx, v);
        hmn = __hmin2(hmn, v);
        float2 f = __half22float2(v);
        smx += f.x; smy += f.y;
        sqx = fmaf(f.x, f.x, sqx);
        sqy = fmaf(f.y, f.y, sqy);
    }

    int deg = s1 - s0;
    float dc = fmaxf((float)deg, 1.f);
    float inv = 1.f / dc;
    float2 uf = *(const float2*)(g_u + (size_t)node*128 + 2*t);

    float vmx_x = __half2float(__low2half(hmx)),  vmx_y = __half2float(__high2half(hmx));
    float vmn_x = __half2float(__low2half(hmn)),  vmn_y = __half2float(__high2half(hmn));
    float vme_x = smx*inv, vme_y = smy*inv;

    float outv[4][2];
    outv[0][0] = deg ? (uf.x + vmx_x) : 0.f;
    outv[0][1] = deg ? (uf.y + vmx_y) : 0.f;
    outv[1][0] = deg ? (uf.x + vmn_x) : 0.f;
    outv[1][1] = deg ? (uf.y + vmn_y) : 0.f;
    outv[2][0] = deg ? (uf.x + vme_x) : 0.f;
    outv[2][1] = deg ? (uf.y + vme_y) : 0.f;
    outv[3][0] = sqrtf(fmaxf(sqx*inv - vme_x*vme_x, 0.f) + 1e-5f);
    outv[3][1] = sqrtf(fmaxf(sqy*inv - vme_y*vme_y, 0.f) + 1e-5f);

    // blocked write: agg col c = a*128 + 2t -> chunk = a*4 + (t>>4), off = (2t)&31
    size_t base = (size_t)(node >> 7)*16*BLKH + (node & 127)*PITCH;
    int off = (2*t) & 31;
    int csub = t >> 4;
    #pragma unroll
    for (int a = 0; a < 4; a++){
        __half2 h = __floats2half2_rn(outv[a][0], outv[a][1]);
        *(__half2*)(g_aggb + base + (size_t)(a*4 + csub)*BLKH + off) = h;
    }

    if (t == 0){
        float ld = logf(dc + 1.f);   // DELTA = 1.0
        g_amp[node] = ld;
        g_att[node] = 1.f / ld;
    }
}

// ---------------- factored FP16 post GEMM (bulk-copy pipelined) --------------
#define P_STAGE (4*BLKH)
#define POST_SMEM_BYTES (2*P_STAGE*2)

__global__ void __launch_bounds__(256, 1)
k_post3(int M, float* __restrict__ C)
{
    extern __shared__ __align__(16) __half smh[];
    __shared__ __align__(16) uint64_t barsto[2];

    int tid  = threadIdx.x;
    int bi   = blockIdx.x;
    int m0   = bi * 128;
    int wid  = tid >> 5, lane = tid & 31;
    int wm   = (wid >> 1) * 32;
    int wn   = (wid & 1) * 64;
    int grp  = lane >> 2, qid = lane & 3;

    int arow  = (lane & 7) + ((lane >> 3) & 1) * 8;
    int aksel = (lane >> 4) * 8;
    int brow  = (lane & 7) + ((lane >> 4) ? 8 : 0);
    int bksel = ((lane >> 3) & 1) * 8;

    uint32_t bars[2] = { s2u(&barsto[0]), s2u(&barsto[1]) };
    if (tid == 0){ mbar_init(bars[0], 1); mbar_init(bars[1], 1); }
    __syncthreads();

    float accC[2][8][4], accA[2][8][4], accT[2][8][4];
    #pragma unroll
    for (int mt = 0; mt < 2; mt++)
        #pragma unroll
        for (int nt = 0; nt < 8; nt++)
            #pragma unroll
            for (int q = 0; q < 4; q++){
                accC[mt][nt][q] = 0.f; accA[mt][nt][q] = 0.f; accT[mt][nt][q] = 0.f;
            }

    auto issue = [&](int t){
        int buf = t & 1;
        uint32_t sA  = s2u(&smh[buf*P_STAGE]);
        if (t < 4){
            mbar_expect_tx(bars[buf], 2*BLKB);
            bulk_g2s(sA,        g_xb + ((size_t)bi*4 + t)*BLKH, BLKB, bars[buf]);
            bulk_g2s(sA + BLKB, g_wcb + (size_t)t*BLKH,         BLKB, bars[buf]);
        } else {
            int ka = t - 4;
            mbar_expect_tx(bars[buf], 4*BLKB);
            bulk_g2s(sA,          g_aggb + ((size_t)bi*16 + ka)*BLKH, BLKB, bars[buf]);
            bulk_g2s(sA + 1*BLKB, g_wcb + (size_t)(4  + ka)*BLKH,     BLKB, bars[buf]);
            bulk_g2s(sA + 2*BLKB, g_wcb + (size_t)(20 + ka)*BLKH,     BLKB, bars[buf]);
            bulk_g2s(sA + 3*BLKB, g_wcb + (size_t)(36 + ka)*BLKH,     BLKB, bars[buf]);
        }
    };

    const int T = 20;
    if (tid == 0){ issue(0); issue(1); }

    for (int t = 0; t < T; t++){
        int cur = t & 1;
        mbar_wait(bars[cur], (t >> 1) & 1);
        const __half* S = &smh[cur*P_STAGE];
        int nsets = (t < 4) ? 1 : 3;
        #pragma unroll
        for (int ks = 0; ks < 2; ks++){
            int kk = ks*16;
            uint32_t a[2][4];
            #pragma unroll
            for (int mt = 0; mt < 2; mt++){
                uint32_t addr = s2u(&S[(wm + mt*16 + arow)*PITCH + kk + aksel]);
                LDSM_X4(a[mt][0], a[mt][1], a[mt][2], a[mt][3], addr);
            }
            #pragma unroll
            for (int s = 0; s < 3; s++){
                if (s >= nsets) break;
                const __half* W = S + (1 + s)*BLKH;
                uint32_t b[8][2];
                #pragma unroll
                for (int p = 0; p < 4; p++){
                    uint32_t addr = s2u(&W[(wn + p*16 + brow)*PITCH + kk + bksel]);
                    LDSM_X4(b[2*p][0], b[2*p][1], b[2*p+1][0], b[2*p+1][1], addr);
                }
                float (*acc)[8][4] = (s == 0) ? accC : (s == 1) ? accA : accT;
                #pragma unroll
                for (int mt = 0; mt < 2; mt++)
                    #pragma unroll
                    for (int nt = 0; nt < 8; nt++)
                        MMA_F16(acc[mt][nt], a[mt][0],a[mt][1],a[mt][2],a[mt][3],
                                b[nt][0], b[nt][1]);
            }
        }
        __syncthreads();
        if (t + 2 < T && tid == 0) issue(t + 2);
    }

    #pragma unroll
    for (int mt = 0; mt < 2; mt++){
        int row0 = m0 + wm + mt*16 + grp;
        int row1 = row0 + 8;
        float amp0 = 0.f, att0 = 0.f, amp1 = 0.f, att1 = 0.f;
        if (row0 < M){ amp0 = g_amp[row0]; att0 = g_att[row0]; }
        if (row1 < M){ amp1 = g_amp[row1]; att1 = g_att[row1]; }
        #pragma unroll
        for (int nt = 0; nt < 8; nt++){
            int col = wn + nt*8 + 2*qid;
            float b0 = g_b_comb[col], b1 = g_b_comb[col+1];
            if (row0 < M){
                float2 v;
                v.x = accC[mt][nt][0] + amp0*accA[mt][nt][0] + att0*accT[mt][nt][0] + b0;
                v.y = accC[mt][nt][1] + amp0*accA[mt][nt][1] + att0*accT[mt][nt][1] + b1;
                *(float2*)(C + (size_t)row0*128 + col) = v;
            }
            if (row1 < M){
                float2 v;
                v.x = accC[mt][nt][2] + amp1*accA[mt][nt][2] + att1*accT[mt][nt][2] + b0;
                v.y = accC[mt][nt][3] + amp1*accA[mt][nt][3] + att1*accT[mt][nt][3] + b1;
                *(float2*)(C + (size_t)row1*128 + col) = v;
            }
        }
    }
}

// ---------------- launch -----------------------------------------------------
extern "C" void kernel_launch(void* const* d_in, const int* in_sizes, int n_in,
                              void* d_out, int out_size)
{
    const float* x      = (const float*)d_in[0];
    const int*   ei     = (const int*)  d_in[1];
    const float* W_pre  = (const float*)d_in[2];
    const float* b_pre  = (const float*)d_in[3];
    const float* W_post = (const float*)d_in[4];
    const float* b_post = (const float*)d_in[5];
    const float* W_lin  = (const float*)d_in[6];
    const float* b_lin  = (const float*)d_in[7];
    float* out = (float*)d_out;

    int N = in_sizes[0] / FDIM;
    int E = in_sizes[1] / 2;
    const int* src = ei;        // edge_index[0] = x_j (source)
    const int* dst = ei + E;    // edge_index[1] = x_i (destination)

    cudaFuncSetAttribute(k_post3,
                         cudaFuncAttributeMaxDynamicSharedMemorySize, POST_SMEM_BYTES);

    // CSR build (k_scan re-zeroes g_deg for next replay)
    k_hist   <<<(E+255)/256, 256>>>(dst, E);
    k_scan   <<<1, 1024>>>(N);
    k_scatter<<<(E+255)/256, 256>>>(src, dst, E);

    // vectorized prep (blocked layouts) + combined weights
    k_prep<<<(N*32+255)/256, 256>>>(x, W_pre, W_lin, N);
    k_combine<<<KPOST+1, FDIM>>>(W_post, b_post, b_lin);

    // u/v fp16 GEMM (bulk pipelined)
    int gm = (N + 127)/128;
    dim3 guv(gm, 2);
    k_uv_f16<<<guv, 256>>>(N, b_pre);

    // factored aggregation (R11, blocked agg out)
    k_agg<<<(N+1)/2, 128>>>(N);

    // factored fp16 post GEMM (bulk pipelined)
    k_post3<<<gm, 256, POST_SMEM_BYTES>>>(N, out);
}

// round 15
// speedup vs baseline: 1.1077x; 1.0212x over previous
#include <cuda_runtime.h>
#include <cuda_fp16.h>
#include <math.h>
#include <stdint.h>

#define FDIM 128
#define NMAX 50000
#define EMAX 800000
#define KPOST (13*FDIM)   /* 1664 */
#define NT    ((NMAX + 127)/128)   /* 391 m-tiles */
#define PITCH 40                   /* halves per smem/blocked row */
#define BLKH  (128*PITCH)          /* halves per block: 5120 */
#define BLKB  (BLKH*2)             /* bytes per block: 10240 */

// ---------------- scratch (static device globals; no allocation) -------------
__device__ __align__(16) int    g_deg[NMAX];                      // stays zeroed between runs
__device__ __align__(16) int    g_rowptr[NMAX+1];
__device__ __align__(16) int    g_cursor[NMAX];
__device__ __align__(16) int    g_srcs[EMAX];
__device__ __align__(16) float  g_u[(size_t)NMAX*FDIM];
__device__ __align__(16) __half g_vh[(size_t)NMAX*FDIM];          // fp16 v (row-major)
__device__ __align__(16) __half g_xb[(size_t)NT*4*BLKH];          // x, chunk-blocked
__device__ __align__(16) __half g_aggb[(size_t)NT*16*BLKH];       // agg, chunk-blocked
__device__ __align__(16) float  g_amp[NMAX];
__device__ __align__(16) float  g_att[NMAX];
__device__ __align__(16) __half g_wuvb[2*4*BLKH];                 // W_uv, blocked
__device__ __align__(16) float  g_Wt_lin[FDIM*FDIM];              // [128][128] (k-major)
__device__ __align__(16) __half g_wcb[52*BLKH];                   // W_comb, blocked
__device__ __align__(16) float  g_b_comb[FDIM];

__device__ __forceinline__ uint32_t s2u(const void* p){
    return (uint32_t)__cvta_generic_to_shared(p);
}

// ---- cp.async.bulk (non-tensor) + mbarrier ----------------------------------
__device__ __forceinline__ void bulk_g2s(uint32_t dst, const void* src,
                                         uint32_t bytes, uint32_t mbar){
    uint64_t g;
    asm("cvta.to.global.u64 %0, %1;" : "=l"(g) : "l"(src));
    asm volatile(
        "cp.async.bulk.shared::cta.global.mbarrier::complete_tx::bytes "
        "[%0], [%1], %2, [%3];"
        :: "r"(dst), "l"(g), "r"(bytes), "r"(mbar) : "memory");
}
__device__ __forceinline__ void mbar_init(uint32_t mbar, uint32_t cnt){
    asm volatile("mbarrier.init.shared.b64 [%0], %1;" :: "r"(mbar), "r"(cnt) : "memory");
}
__device__ __forceinline__ void mbar_expect_tx(uint32_t mbar, uint32_t bytes){
    asm volatile("mbarrier.arrive.expect_tx.shared.b64 _, [%0], %1;"
                 :: "r"(mbar), "r"(bytes) : "memory");
}
__device__ __forceinline__ void mbar_wait(uint32_t mbar, uint32_t parity){
    uint32_t done = 0;
    while (!done){
        asm volatile(
            "{\n\t"
            ".reg .pred p;\n\t"
            "mbarrier.try_wait.parity.acquire.cta.shared::cta.b64 p, [%1], %2, 0x989680;\n\t"
            "selp.b32 %0, 1, 0, p;\n\t"
            "}"
            : "=r"(done) : "r"(mbar), "r"(parity) : "memory");
    }
}

#define MMA_F16(acc, a0,a1,a2,a3, b0,b1) \
    asm volatile( \
        "mma.sync.aligned.m16n8k16.row.col.f32.f16.f16.f32 " \
        "{%0,%1,%2,%3}, {%4,%5,%6,%7}, {%8,%9}, {%0,%1,%2,%3};\n" \
        : "+f"((acc)[0]), "+f"((acc)[1]), "+f"((acc)[2]), "+f"((acc)[3]) \
        : "r"(a0), "r"(a1), "r"(a2), "r"(a3), "r"(b0), "r"(b1))

#define LDSM_X4(r0,r1,r2,r3,addr) \
    asm volatile("ldmatrix.sync.aligned.m8n8.x4.shared.b16 {%0,%1,%2,%3}, [%4];" \
        : "=r"(r0), "=r"(r1), "=r"(r2), "=r"(r3) : "r"(addr))

// ---------------- CSR build --------------------------------------------------
__global__ void k_hist(const int* __restrict__ dst, int E){
    int e = blockIdx.x*blockDim.x + threadIdx.x;
    if (e < E) atomicAdd(&g_deg[dst[e]], 1);
}

// scan also re-zeroes g_deg for the next graph replay
__global__ void k_scan(int n){
    __shared__ int ss[1024];
    int t = threadIdx.x;
    int chunk = (n + 1023) >> 10;
    int lo = t*chunk;
    int hi = min(lo + chunk, n);
    int s = 0;
    for (int i = lo; i < hi; i++) s += g_deg[i];
    ss[t] = s;
    __syncthreads();
    for (int off = 1; off < 1024; off <<= 1){
        int v = (t >= off) ? ss[t-off] : 0;
        __syncthreads();
        ss[t] += v;
        __syncthreads();
    }
    int run = (t == 0) ? 0 : ss[t-1];
    for (int i = lo; i < hi; i++){
        g_rowptr[i] = run;
        g_cursor[i] = run;
        run += g_deg[i];
        g_deg[i] = 0;
    }
    if (t == 1023) g_rowptr[n] = ss[1023];
}

__global__ void k_scatter(const int* __restrict__ src, const int* __restrict__ dst, int E){
    int e = blockIdx.x*blockDim.x + threadIdx.x;
    if (e < E){
        int d = dst[e];
        int p = atomicAdd(&g_cursor[d], 1);
        g_srcs[p] = src[e];
    }
}

// ---------------- vectorized prep: blocked x + blocked Wuv + lin-transpose ---
__global__ void k_prep(const float* __restrict__ x, const float* __restrict__ W_pre,
                       const float* __restrict__ W_lin, int N){
    int stride = gridDim.x*blockDim.x;
    int i0 = blockIdx.x*blockDim.x + threadIdx.x;
    for (int i = i0; i < N*32; i += stride){
        int node = i >> 5, c4 = i & 31;
        float4 v = *(const float4*)(x + (size_t)node*128 + c4*4);
        size_t dst = ((size_t)(node >> 7)*4 + (c4 >> 3))*BLKH
                   + (size_t)(node & 127)*PITCH + (c4 & 7)*4;
        *(__half2*)(g_xb + dst)     = __floats2half2_rn(v.x, v.y);
        *(__half2*)(g_xb + dst + 2) = __floats2half2_rn(v.z, v.w);
    }
    for (int i = i0; i < 256*32; i += stride){
        int j = i >> 5, k4 = i & 31;
        float4 v = *(const float4*)(W_pre + (size_t)(j & 127)*256
                                    + ((j >> 7) ? 128 : 0) + k4*4);
        size_t dst = ((size_t)(j >> 7)*4 + (k4 >> 3))*BLKH
                   + (size_t)(j & 127)*PITCH + (k4 & 7)*4;
        *(__half2*)(g_wuvb + dst)     = __floats2half2_rn(v.x, v.y);
        *(__half2*)(g_wuvb + dst + 2) = __floats2half2_rn(v.z, v.w);
    }
    for (int i = i0; i < FDIM*FDIM; i += stride){
        int f = i >> 7, c = i & 127;
        g_Wt_lin[c*FDIM + f] = W_lin[i];
    }
}

// blocked W_comb: g_wcb[chunk=c>>5][f][c&31]; block KPOST computes bias
__global__ void k_combine(const float* __restrict__ W_post,
                          const float* __restrict__ b_post,
                          const float* __restrict__ b_lin){
    int f = threadIdx.x;
    if (blockIdx.x == KPOST){
        float s = b_lin[f];
        #pragma unroll 8
        for (int k = 0; k < FDIM; k++)
            s = fmaf(g_Wt_lin[k*FDIM + f], b_post[k], s);
        g_b_comb[f] = s;
        return;
    }
    int c = blockIdx.x;
    __shared__ float col[FDIM];
    col[f] = W_post[(size_t)f*KPOST + c];
    __syncthreads();
    float s = 0.f;
    #pragma unroll 8
    for (int k = 0; k < FDIM; k++)
        s = fmaf(g_Wt_lin[k*FDIM + f], col[k], s);
    g_wcb[(size_t)(c >> 5)*BLKH + f*PITCH + (c & 31)] = __float2half_rn(s);
}

// ---------------- u/v FP16 GEMM: bulk-copy pipelined (K=128) -----------------
__global__ void __launch_bounds__(256, 2)
k_uv_f16(int M, const float* __restrict__ b_pre)
{
    __shared__ __align__(16) __half st[2][2*BLKH];   // [stage][A | W]
    __shared__ __align__(16) uint64_t barsto[2];

    int tid  = threadIdx.x;
    int bi   = blockIdx.x;
    int m0   = bi * 128;
    int half_ = blockIdx.y;
    int wid  = tid >> 5, lane = tid & 31;
    int wm   = (wid >> 1) * 32;
    int wn   = (wid & 1) * 64;
    int grp  = lane >> 2, qid = lane & 3;

    int arow  = (lane & 7) + ((lane >> 3) & 1) * 8;
    int aksel = (lane >> 4) * 8;
    int brow  = (lane & 7) + ((lane >> 4) ? 8 : 0);
    int bksel = ((lane >> 3) & 1) * 8;

    uint32_t bars[2] = { s2u(&barsto[0]), s2u(&barsto[1]) };
    if (tid == 0){ mbar_init(bars[0], 1); mbar_init(bars[1], 1); }
    __syncthreads();

    float acc[2][8][4];
    #pragma unroll
    for (int mt = 0; mt < 2; mt++)
        #pragma unroll
        for (int nt = 0; nt < 8; nt++)
            #pragma unroll
            for (int q = 0; q < 4; q++) acc[mt][nt][q] = 0.f;

    auto issue = [&](int t){
        int buf = t & 1;
        mbar_expect_tx(bars[buf], 2*BLKB);
        bulk_g2s(s2u(&st[buf][0]),    g_xb + ((size_t)bi*4 + t)*BLKH,      BLKB, bars[buf]);
        bulk_g2s(s2u(&st[buf][BLKH]), g_wuvb + ((size_t)half_*4 + t)*BLKH, BLKB, bars[buf]);
    };

    const int T = 4;
    if (tid == 0){ issue(0); issue(1); }

    for (int t = 0; t < T; t++){
        int cur = t & 1;
        mbar_wait(bars[cur], (t >> 1) & 1);
        const __half* A = &st[cur][0];
        const __half* W = &st[cur][BLKH];
        #pragma unroll
        for (int ks = 0; ks < 2; ks++){
            int kk = ks*16;
            uint32_t a[2][4], b[8][2];
            #pragma unroll
            for (int mt = 0; mt < 2; mt++){
                uint32_t addr = s2u(&A[(wm + mt*16 + arow)*PITCH + kk + aksel]);
                LDSM_X4(a[mt][0], a[mt][1], a[mt][2], a[mt][3], addr);
            }
            #pragma unroll
            for (int p = 0; p < 4; p++){
                uint32_t addr = s2u(&W[(wn + p*16 + brow)*PITCH + kk + bksel]);
                LDSM_X4(b[2*p][0], b[2*p][1], b[2*p+1][0], b[2*p+1][1], addr);
            }
            #pragma unroll
            for (int mt = 0; mt < 2; mt++)
                #pragma unroll
                for (int nt = 0; nt < 8; nt++)
                    MMA_F16(acc[mt][nt], a[mt][0],a[mt][1],a[mt][2],a[mt][3],
                            b[nt][0], b[nt][1]);
        }
        __syncthreads();
        if (t + 2 < T && tid == 0) issue(t + 2);
    }

    #pragma unroll
    for (int mt = 0; mt < 2; mt++){
        int row0 = m0 + wm + mt*16 + grp;
        #pragma unroll
        for (int nt = 0; nt < 8; nt++){
            int col = wn + nt*8 + 2*qid;
            if (half_){
                if (row0 < M)
                    *(__half2*)(g_vh + (size_t)row0*128 + col) =
                        __floats2half2_rn(acc[mt][nt][0], acc[mt][nt][1]);
                if (row0 + 8 < M)
                    *(__half2*)(g_vh + (size_t)(row0+8)*128 + col) =
                        __floats2half2_rn(acc[mt][nt][2], acc[mt][nt][3]);
            } else {
                float b0 = b_pre[col], b1 = b_pre[col+1];
                if (row0 < M)
                    *(float2*)(g_u + (size_t)row0*128 + col) =
                        make_float2(acc[mt][nt][0] + b0, acc[mt][nt][1] + b1);
                if (row0 + 8 < M)
                    *(float2*)(g_u + (size_t)(row0+8)*128 + col) =
                        make_float2(acc[mt][nt][2] + b0, acc[mt][nt][3] + b1);
            }
        }
    }
}

// ---------------- per-node aggregation: 32 thr/node, uint2 (4-feature) loads -
__global__ void k_agg(int n){
    int node = blockIdx.x*4 + (threadIdx.x >> 5);
    int t = threadIdx.x & 31;          // features 4t..4t+3
    if (node >= n) return;
    int s0 = g_rowptr[node], s1 = g_rowptr[node+1];
    const uint2* vh = (const uint2*)g_vh;   // row stride = 32 uint2

    const __half2 NEG = __half2half2(__ushort_as_half((unsigned short)0xFC00));
    const __half2 POS = __half2half2(__ushort_as_half((unsigned short)0x7C00));
    __half2 mx0 = NEG, mx1 = NEG, mn0 = POS, mn1 = POS;
    float sm0=0.f,sm1=0.f,sm2=0.f,sm3=0.f, sq0=0.f,sq1=0.f,sq2=0.f,sq3=0.f;

    auto accum = [&](uint2 r){
        __half2 ha = *(__half2*)&r.x, hb = *(__half2*)&r.y;
        mx0 = __hmax2(mx0, ha); mx1 = __hmax2(mx1, hb);
        mn0 = __hmin2(mn0, ha); mn1 = __hmin2(mn1, hb);
        float2 fa = __half22float2(ha), fb = __half22float2(hb);
        sm0 += fa.x; sm1 += fa.y; sm2 += fb.x; sm3 += fb.y;
        sq0 = fmaf(fa.x, fa.x, sq0); sq1 = fmaf(fa.y, fa.y, sq1);
        sq2 = fmaf(fb.x, fb.x, sq2); sq3 = fmaf(fb.y, fb.y, sq3);
    };

    int e = s0;
    for (; e + 3 < s1; e += 4){
        int i0 = g_srcs[e], i1 = g_srcs[e+1], i2 = g_srcs[e+2], i3 = g_srcs[e+3];
        uint2 r0 = vh[(size_t)i0*32 + t];
        uint2 r1 = vh[(size_t)i1*32 + t];
        uint2 r2 = vh[(size_t)i2*32 + t];
        uint2 r3 = vh[(size_t)i3*32 + t];
        accum(r0); accum(r1); accum(r2); accum(r3);
    }
    for (; e < s1; e++){
        int s = g_srcs[e];
        accum(vh[(size_t)s*32 + t]);
    }

    int deg = s1 - s0;
    float dc = fmaxf((float)deg, 1.f);
    float inv = 1.f / dc;
    float4 uf = *(const float4*)(g_u + (size_t)node*128 + 4*t);

    float mxf[4] = { __half2float(__low2half(mx0)), __half2float(__high2half(mx0)),
                     __half2float(__low2half(mx1)), __half2float(__high2half(mx1)) };
    float mnf[4] = { __half2float(__low2half(mn0)), __half2float(__high2half(mn0)),
                     __half2float(__low2half(mn1)), __half2float(__high2half(mn1)) };
    float mef[4] = { sm0*inv, sm1*inv, sm2*inv, sm3*inv };
    float sqf[4] = { sq0, sq1, sq2, sq3 };
    float ufv[4] = { uf.x, uf.y, uf.z, uf.w };

    float o[4][4];
    #pragma unroll
    for (int j = 0; j < 4; j++){
        o[0][j] = deg ? (ufv[j] + mxf[j]) : 0.f;
        o[1][j] = deg ? (ufv[j] + mnf[j]) : 0.f;
        o[2][j] = deg ? (ufv[j] + mef[j]) : 0.f;
        o[3][j] = sqrtf(fmaxf(sqf[j]*inv - mef[j]*mef[j], 0.f) + 1e-5f);
    }

    // blocked write: col c = a*128 + 4t + j -> chunk = a*4 + (t>>3), off = (4t)&31
    size_t base = (size_t)(node >> 7)*16*BLKH + (size_t)(node & 127)*PITCH + ((4*t) & 31);
    int csub = t >> 3;
    #pragma unroll
    for (int a = 0; a < 4; a++){
        __half2 h0 = __floats2half2_rn(o[a][0], o[a][1]);
        __half2 h1 = __floats2half2_rn(o[a][2], o[a][3]);
        uint2 pack;
        pack.x = *(uint32_t*)&h0;
        pack.y = *(uint32_t*)&h1;
        *(uint2*)(g_aggb + base + (size_t)(a*4 + csub)*BLKH) = pack;
    }

    if (t == 0){
        float ld = logf(dc + 1.f);   // DELTA = 1.0
        g_amp[node] = ld;
        g_att[node] = 1.f / ld;
    }
}

// ---------------- factored FP16 post GEMM (3-stage bulk pipeline) ------------
#define P_STAGE (4*BLKH)
#define NSTAGE 3
#define POST_SMEM_BYTES (NSTAGE*P_STAGE*2)

__global__ void __launch_bounds__(256, 1)
k_post3(int M, float* __restrict__ C)
{
    extern __shared__ __align__(16) __half smh[];
    __shared__ __align__(16) uint64_t barsto[NSTAGE];

    int tid  = threadIdx.x;
    int bi   = blockIdx.x;
    int m0   = bi * 128;
    int wid  = tid >> 5, lane = tid & 31;
    int wm   = (wid >> 1) * 32;
    int wn   = (wid & 1) * 64;
    int grp  = lane >> 2, qid = lane & 3;

    int arow  = (lane & 7) + ((lane >> 3) & 1) * 8;
    int aksel = (lane >> 4) * 8;
    int brow  = (lane & 7) + ((lane >> 4) ? 8 : 0);
    int bksel = ((lane >> 3) & 1) * 8;

    uint32_t bars[NSTAGE];
    #pragma unroll
    for (int i = 0; i < NSTAGE; i++) bars[i] = s2u(&barsto[i]);
    if (tid == 0){
        #pragma unroll
        for (int i = 0; i < NSTAGE; i++) mbar_init(bars[i], 1);
    }
    __syncthreads();

    float accC[2][8][4], accA[2][8][4], accT[2][8][4];
    #pragma unroll
    for (int mt = 0; mt < 2; mt++)
        #pragma unroll
        for (int nt = 0; nt < 8; nt++)
            #pragma unroll
            for (int q = 0; q < 4; q++){
                accC[mt][nt][q] = 0.f; accA[mt][nt][q] = 0.f; accT[mt][nt][q] = 0.f;
            }

    auto issue = [&](int t, int buf){
        uint32_t sA  = s2u(&smh[buf*P_STAGE]);
        if (t < 4){
            mbar_expect_tx(bars[buf], 2*BLKB);
            bulk_g2s(sA,        g_xb + ((size_t)bi*4 + t)*BLKH, BLKB, bars[buf]);
            bulk_g2s(sA + BLKB, g_wcb + (size_t)t*BLKH,         BLKB, bars[buf]);
        } else {
            int ka = t - 4;
            mbar_expect_tx(bars[buf], 4*BLKB);
            bulk_g2s(sA,          g_aggb + ((size_t)bi*16 + ka)*BLKH, BLKB, bars[buf]);
            bulk_g2s(sA + 1*BLKB, g_wcb + (size_t)(4  + ka)*BLKH,     BLKB, bars[buf]);
            bulk_g2s(sA + 2*BLKB, g_wcb + (size_t)(20 + ka)*BLKH,     BLKB, bars[buf]);
            bulk_g2s(sA + 3*BLKB, g_wcb + (size_t)(36 + ka)*BLKH,     BLKB, bars[buf]);
        }
    };

    const int T = 20;
    if (tid == 0){ issue(0, 0); issue(1, 1); issue(2, 2); }

    int cur = 0, ph = 0;
    for (int t = 0; t < T; t++){
        mbar_wait(bars[cur], ph);
        const __half* S = &smh[cur*P_STAGE];
        int nsets = (t < 4) ? 1 : 3;
        #pragma unroll
        for (int ks = 0; ks < 2; ks++){
            int kk = ks*16;
            uint32_t a[2][4];
            #pragma unroll
            for (int mt = 0; mt < 2; mt++){
                uint32_t addr = s2u(&S[(wm + mt*16 + arow)*PITCH + kk + aksel]);
                LDSM_X4(a[mt][0], a[mt][1], a[mt][2], a[mt][3], addr);
            }
            #pragma unroll
            for (int s = 0; s < 3; s++){
                if (s >= nsets) break;
                const __half* W = S + (1 + s)*BLKH;
                uint32_t b[8][2];
                #pragma unroll
                for (int p = 0; p < 4; p++){
                    uint32_t addr = s2u(&W[(wn + p*16 + brow)*PITCH + kk + bksel]);
                    LDSM_X4(b[2*p][0], b[2*p][1], b[2*p+1][0], b[2*p+1][1], addr);
                }
                float (*acc)[8][4] = (s == 0) ? accC : (s == 1) ? accA : accT;
                #pragma unroll
                for (int mt = 0; mt < 2; mt++)
                    #pragma unroll
                    for (int nt = 0; nt < 8; nt++)
                        MMA_F16(acc[mt][nt], a[mt][0],a[mt][1],a[mt][2],a[mt][3],
                                b[nt][0], b[nt][1]);
            }
        }
        __syncthreads();
        if (t + NSTAGE < T && tid == 0) issue(t + NSTAGE, cur);
        cur++;
        if (cur == NSTAGE){ cur = 0; ph ^= 1; }
    }

    #pragma unroll
    for (int mt = 0; mt < 2; mt++){
        int row0 = m0 + wm + mt*16 + grp;
        int row1 = row0 + 8;
        float amp0 = 0.f, att0 = 0.f, amp1 = 0.f, att1 = 0.f;
        if (row0 < M){ amp0 = g_amp[row0]; att0 = g_att[row0]; }
        if (row1 < M){ amp1 = g_amp[row1]; att1 = g_att[row1]; }
        #pragma unroll
        for (int nt = 0; nt < 8; nt++){
            int col = wn + nt*8 + 2*qid;
            float b0 = g_b_comb[col], b1 = g_b_comb[col+1];
            if (row0 < M){
                float2 v;
                v.x = accC[mt][nt][0] + amp0*accA[mt][nt][0] + att0*accT[mt][nt][0] + b0;
                v.y = accC[mt][nt][1] + amp0*accA[mt][nt][1] + att0*accT[mt][nt][1] + b1;
                *(float2*)(C + (size_t)row0*128 + col) = v;
            }
            if (row1 < M){
                float2 v;
                v.x = accC[mt][nt][2] + amp1*accA[mt][nt][2] + att1*accT[mt][nt][2] + b0;
                v.y = accC[mt][nt][3] + amp1*accA[mt][nt][3] + att1*accT[mt][nt][3] + b1;
                *(float2*)(C + (size_t)row1*128 + col) = v;
            }
        }
    }
}

// ---------------- launch -----------------------------------------------------
extern "C" void kernel_launch(void* const* d_in, const int* in_sizes, int n_in,
                              void* d_out, int out_size)
{
    const float* x      = (const float*)d_in[0];
    const int*   ei     = (const int*)  d_in[1];
    const float* W_pre  = (const float*)d_in[2];
    const float* b_pre  = (const float*)d_in[3];
    const float* W_post = (const float*)d_in[4];
    const float* b_post = (const float*)d_in[5];
    const float* W_lin  = (const float*)d_in[6];
    const float* b_lin  = (const float*)d_in[7];
    float* out = (float*)d_out;

    int N = in_sizes[0] / FDIM;
    int E = in_sizes[1] / 2;
    const int* src = ei;        // edge_index[0] = x_j (source)
    const int* dst = ei + E;    // edge_index[1] = x_i (destination)

    cudaFuncSetAttribute(k_post3,
                         cudaFuncAttributeMaxDynamicSharedMemorySize, POST_SMEM_BYTES);

    // CSR build (k_scan re-zeroes g_deg for next replay)
    k_hist   <<<(E+255)/256, 256>>>(dst, E);
    k_scan   <<<1, 1024>>>(N);
    k_scatter<<<(E+255)/256, 256>>>(src, dst, E);

    // vectorized prep (blocked layouts) + combined weights
    k_prep<<<(N*32+255)/256, 256>>>(x, W_pre, W_lin, N);
    k_combine<<<KPOST+1, FDIM>>>(W_post, b_post, b_lin);

    // u/v fp16 GEMM (bulk pipelined)
    int gm = (N + 127)/128;
    dim3 guv(gm, 2);
    k_uv_f16<<<guv, 256>>>(N, b_pre);

    // aggregation (32 thr/node, uint2 gathers, blocked agg out)
    k_agg<<<(N+3)/4, 128>>>(N);

    // factored fp16 post GEMM (3-stage bulk pipeline)
    k_post3<<<gm, 256, POST_SMEM_BYTES>>>(N, out);
}

// round 16
// speedup vs baseline: 1.1636x; 1.0504x over previous
#include <cuda_runtime.h>
#include <cuda_fp16.h>
#include <math.h>
#include <stdint.h>

#define FDIM 128
#define NMAX 50000
#define EMAX 800000
#define KPOST (13*FDIM)   /* 1664 */
#define NT    ((NMAX + 127)/128)   /* 391 m-tiles */
#define PITCH 40                   /* halves per smem/blocked row */
#define BLKH  (128*PITCH)          /* halves per block: 5120 */
#define BLKB  (BLKH*2)             /* bytes per block: 10240 */

// ---------------- scratch (static device globals; no allocation) -------------
__device__ __align__(16) int    g_deg[NMAX];                      // stays zeroed between runs
__device__ __align__(16) int    g_rowptr[NMAX+1];
__device__ __align__(16) int    g_cursor[NMAX];
__device__ __align__(16) int    g_srcs[EMAX];
__device__ __align__(16) float  g_u[(size_t)NMAX*FDIM];
__device__ __align__(16) __half g_vh[(size_t)NMAX*FDIM];          // fp16 v (row-major)
__device__ __align__(16) __half g_xb[(size_t)NT*4*BLKH];          // x, chunk-blocked
__device__ __align__(16) __half g_aggb[(size_t)NT*16*BLKH];       // agg, chunk-blocked
__device__ __align__(16) float  g_amp[NMAX];
__device__ __align__(16) float  g_att[NMAX];
__device__ __align__(16) __half g_wuvb[2*4*BLKH];                 // W_uv, blocked
__device__ __align__(16) float  g_Wt_lin[FDIM*FDIM];              // [128][128] (k-major)
__device__ __align__(16) __half g_wcb[52*BLKH];                   // W_comb, blocked
__device__ __align__(16) float  g_b_comb[FDIM];

__device__ __forceinline__ uint32_t s2u(const void* p){
    return (uint32_t)__cvta_generic_to_shared(p);
}

// ---- cp.async.bulk (non-tensor) + mbarrier ----------------------------------
__device__ __forceinline__ void bulk_g2s(uint32_t dst, const void* src,
                                         uint32_t bytes, uint32_t mbar){
    uint64_t g;
    asm("cvta.to.global.u64 %0, %1;" : "=l"(g) : "l"(src));
    asm volatile(
        "cp.async.bulk.shared::cta.global.mbarrier::complete_tx::bytes "
        "[%0], [%1], %2, [%3];"
        :: "r"(dst), "l"(g), "r"(bytes), "r"(mbar) : "memory");
}
__device__ __forceinline__ void mbar_init(uint32_t mbar, uint32_t cnt){
    asm volatile("mbarrier.init.shared.b64 [%0], %1;" :: "r"(mbar), "r"(cnt) : "memory");
}
__device__ __forceinline__ void mbar_expect_tx(uint32_t mbar, uint32_t bytes){
    asm volatile("mbarrier.arrive.expect_tx.shared.b64 _, [%0], %1;"
                 :: "r"(mbar), "r"(bytes) : "memory");
}
__device__ __forceinline__ void mbar_wait(uint32_t mbar, uint32_t parity){
    uint32_t done = 0;
    while (!done){
        asm volatile(
            "{\n\t"
            ".reg .pred p;\n\t"
            "mbarrier.try_wait.parity.acquire.cta.shared::cta.b64 p, [%1], %2, 0x989680;\n\t"
            "selp.b32 %0, 1, 0, p;\n\t"
            "}"
            : "=r"(done) : "r"(mbar), "r"(parity) : "memory");
    }
}

#define MMA_F16(acc, a0,a1,a2,a3, b0,b1) \
    asm volatile( \
        "mma.sync.aligned.m16n8k16.row.col.f32.f16.f16.f32 " \
        "{%0,%1,%2,%3}, {%4,%5,%6,%7}, {%8,%9}, {%0,%1,%2,%3};\n" \
        : "+f"((acc)[0]), "+f"((acc)[1]), "+f"((acc)[2]), "+f"((acc)[3]) \
        : "r"(a0), "r"(a1), "r"(a2), "r"(a3), "r"(b0), "r"(b1))

#define LDSM_X4(r0,r1,r2,r3,addr) \
    asm volatile("ldmatrix.sync.aligned.m8n8.x4.shared.b16 {%0,%1,%2,%3}, [%4];" \
        : "=r"(r0), "=r"(r1), "=r"(r2), "=r"(r3) : "r"(addr))

// ---------------- CSR build --------------------------------------------------
__global__ void k_hist(const int* __restrict__ dst, int E){
    int e = blockIdx.x*blockDim.x + threadIdx.x;
    if (e < E) atomicAdd(&g_deg[dst[e]], 1);
}

// scan also re-zeroes g_deg for the next graph replay
__global__ void k_scan(int n){
    __shared__ int ss[1024];
    int t = threadIdx.x;
    int chunk = (n + 1023) >> 10;
    int lo = t*chunk;
    int hi = min(lo + chunk, n);
    int s = 0;
    for (int i = lo; i < hi; i++) s += g_deg[i];
    ss[t] = s;
    __syncthreads();
    for (int off = 1; off < 1024; off <<= 1){
        int v = (t >= off) ? ss[t-off] : 0;
        __syncthreads();
        ss[t] += v;
        __syncthreads();
    }
    int run = (t == 0) ? 0 : ss[t-1];
    for (int i = lo; i < hi; i++){
        g_rowptr[i] = run;
        g_cursor[i] = run;
        run += g_deg[i];
        g_deg[i] = 0;
    }
    if (t == 1023) g_rowptr[n] = ss[1023];
}

__global__ void k_scatter(const int* __restrict__ src, const int* __restrict__ dst, int E){
    int e = blockIdx.x*blockDim.x + threadIdx.x;
    if (e < E){
        int d = dst[e];
        int p = atomicAdd(&g_cursor[d], 1);
        g_srcs[p] = src[e];
    }
}

// ---------------- vectorized prep: blocked x + blocked Wuv + lin-transpose ---
__global__ void k_prep(const float* __restrict__ x, const float* __restrict__ W_pre,
                       const float* __restrict__ W_lin, int N){
    int stride = gridDim.x*blockDim.x;
    int i0 = blockIdx.x*blockDim.x + threadIdx.x;
    for (int i = i0; i < N*32; i += stride){
        int node = i >> 5, c4 = i & 31;
        float4 v = *(const float4*)(x + (size_t)node*128 + c4*4);
        size_t dst = ((size_t)(node >> 7)*4 + (c4 >> 3))*BLKH
                   + (size_t)(node & 127)*PITCH + (c4 & 7)*4;
        *(__half2*)(g_xb + dst)     = __floats2half2_rn(v.x, v.y);
        *(__half2*)(g_xb + dst + 2) = __floats2half2_rn(v.z, v.w);
    }
    for (int i = i0; i < 256*32; i += stride){
        int j = i >> 5, k4 = i & 31;
        float4 v = *(const float4*)(W_pre + (size_t)(j & 127)*256
                                    + ((j >> 7) ? 128 : 0) + k4*4);
        size_t dst = ((size_t)(j >> 7)*4 + (k4 >> 3))*BLKH
                   + (size_t)(j & 127)*PITCH + (k4 & 7)*4;
        *(__half2*)(g_wuvb + dst)     = __floats2half2_rn(v.x, v.y);
        *(__half2*)(g_wuvb + dst + 2) = __floats2half2_rn(v.z, v.w);
    }
    for (int i = i0; i < FDIM*FDIM; i += stride){
        int f = i >> 7, c = i & 127;
        g_Wt_lin[c*FDIM + f] = W_lin[i];
    }
}

// blocked W_comb: g_wcb[chunk=c>>5][f][c&31]; block KPOST computes bias
__global__ void k_combine(const float* __restrict__ W_post,
                          const float* __restrict__ b_post,
                          const float* __restrict__ b_lin){
    int f = threadIdx.x;
    if (blockIdx.x == KPOST){
        float s = b_lin[f];
        #pragma unroll 8
        for (int k = 0; k < FDIM; k++)
            s = fmaf(g_Wt_lin[k*FDIM + f], b_post[k], s);
        g_b_comb[f] = s;
        return;
    }
    int c = blockIdx.x;
    __shared__ float col[FDIM];
    col[f] = W_post[(size_t)f*KPOST + c];
    __syncthreads();
    float s = 0.f;
    #pragma unroll 8
    for (int k = 0; k < FDIM; k++)
        s = fmaf(g_Wt_lin[k*FDIM + f], col[k], s);
    g_wcb[(size_t)(c >> 5)*BLKH + f*PITCH + (c & 31)] = __float2half_rn(s);
}

// ---------------- u/v FP16 GEMM: bulk-copy pipelined (K=128) -----------------
__global__ void __launch_bounds__(256, 2)
k_uv_f16(int M, const float* __restrict__ b_pre)
{
    __shared__ __align__(16) __half st[2][2*BLKH];   // [stage][A | W]
    __shared__ __align__(16) uint64_t barsto[2];

    int tid  = threadIdx.x;
    int bi   = blockIdx.x;
    int m0   = bi * 128;
    int half_ = blockIdx.y;
    int wid  = tid >> 5, lane = tid & 31;
    int wm   = (wid >> 1) * 32;
    int wn   = (wid & 1) * 64;
    int grp  = lane >> 2, qid = lane & 3;

    int arow  = (lane & 7) + ((lane >> 3) & 1) * 8;
    int aksel = (lane >> 4) * 8;
    int brow  = (lane & 7) + ((lane >> 4) ? 8 : 0);
    int bksel = ((lane >> 3) & 1) * 8;

    uint32_t bars[2] = { s2u(&barsto[0]), s2u(&barsto[1]) };
    if (tid == 0){ mbar_init(bars[0], 1); mbar_init(bars[1], 1); }
    __syncthreads();

    float acc[2][8][4];
    #pragma unroll
    for (int mt = 0; mt < 2; mt++)
        #pragma unroll
        for (int nt = 0; nt < 8; nt++)
            #pragma unroll
            for (int q = 0; q < 4; q++) acc[mt][nt][q] = 0.f;

    auto issue = [&](int t){
        int buf = t & 1;
        mbar_expect_tx(bars[buf], 2*BLKB);
        bulk_g2s(s2u(&st[buf][0]),    g_xb + ((size_t)bi*4 + t)*BLKH,      BLKB, bars[buf]);
        bulk_g2s(s2u(&st[buf][BLKH]), g_wuvb + ((size_t)half_*4 + t)*BLKH, BLKB, bars[buf]);
    };

    const int T = 4;
    if (tid == 0){ issue(0); issue(1); }

    for (int t = 0; t < T; t++){
        int cur = t & 1;
        mbar_wait(bars[cur], (t >> 1) & 1);
        const __half* A = &st[cur][0];
        const __half* W = &st[cur][BLKH];
        #pragma unroll
        for (int ks = 0; ks < 2; ks++){
            int kk = ks*16;
            uint32_t a[2][4], b[8][2];
            #pragma unroll
            for (int mt = 0; mt < 2; mt++){
                uint32_t addr = s2u(&A[(wm + mt*16 + arow)*PITCH + kk + aksel]);
                LDSM_X4(a[mt][0], a[mt][1], a[mt][2], a[mt][3], addr);
            }
            #pragma unroll
            for (int p = 0; p < 4; p++){
                uint32_t addr = s2u(&W[(wn + p*16 + brow)*PITCH + kk + bksel]);
                LDSM_X4(b[2*p][0], b[2*p][1], b[2*p+1][0], b[2*p+1][1], addr);
            }
            #pragma unroll
            for (int mt = 0; mt < 2; mt++)
                #pragma unroll
                for (int nt = 0; nt < 8; nt++)
                    MMA_F16(acc[mt][nt], a[mt][0],a[mt][1],a[mt][2],a[mt][3],
                            b[nt][0], b[nt][1]);
        }
        __syncthreads();
        if (t + 2 < T && tid == 0) issue(t + 2);
    }

    #pragma unroll
    for (int mt = 0; mt < 2; mt++){
        int row0 = m0 + wm + mt*16 + grp;
        #pragma unroll
        for (int nt = 0; nt < 8; nt++){
            int col = wn + nt*8 + 2*qid;
            if (half_){
                if (row0 < M)
                    *(__half2*)(g_vh + (size_t)row0*128 + col) =
                        __floats2half2_rn(acc[mt][nt][0], acc[mt][nt][1]);
                if (row0 + 8 < M)
                    *(__half2*)(g_vh + (size_t)(row0+8)*128 + col) =
                        __floats2half2_rn(acc[mt][nt][2], acc[mt][nt][3]);
            } else {
                float b0 = b_pre[col], b1 = b_pre[col+1];
                if (row0 < M)
                    *(float2*)(g_u + (size_t)row0*128 + col) =
                        make_float2(acc[mt][nt][0] + b0, acc[mt][nt][1] + b1);
                if (row0 + 8 < M)
                    *(float2*)(g_u + (size_t)(row0+8)*128 + col) =
                        make_float2(acc[mt][nt][2] + b0, acc[mt][nt][3] + b1);
            }
        }
    }
}

// ---------------- per-node aggregation: 32 thr/node, uint2 (4-feature) loads -
__global__ void k_agg(int n){
    int node = blockIdx.x*4 + (threadIdx.x >> 5);
    int t = threadIdx.x & 31;          // features 4t..4t+3
    if (node >= n) return;
    int s0 = g_rowptr[node], s1 = g_rowptr[node+1];
    const uint2* vh = (const uint2*)g_vh;   // row stride = 32 uint2

    const __half2 NEG = __half2half2(__ushort_as_half((unsigned short)0xFC00));
    const __half2 POS = __half2half2(__ushort_as_half((unsigned short)0x7C00));
    __half2 mx0 = NEG, mx1 = NEG, mn0 = POS, mn1 = POS;
    float sm0=0.f,sm1=0.f,sm2=0.f,sm3=0.f, sq0=0.f,sq1=0.f,sq2=0.f,sq3=0.f;

    auto accum = [&](uint2 r){
        __half2 ha = *(__half2*)&r.x, hb = *(__half2*)&r.y;
        mx0 = __hmax2(mx0, ha); mx1 = __hmax2(mx1, hb);
        mn0 = __hmin2(mn0, ha); mn1 = __hmin2(mn1, hb);
        float2 fa = __half22float2(ha), fb = __half22float2(hb);
        sm0 += fa.x; sm1 += fa.y; sm2 += fb.x; sm3 += fb.y;
        sq0 = fmaf(fa.x, fa.x, sq0); sq1 = fmaf(fa.y, fa.y, sq1);
        sq2 = fmaf(fb.x, fb.x, sq2); sq3 = fmaf(fb.y, fb.y, sq3);
    };

    int e = s0;
    for (; e + 3 < s1; e += 4){
        int i0 = g_srcs[e], i1 = g_srcs[e+1], i2 = g_srcs[e+2], i3 = g_srcs[e+3];
        uint2 r0 = vh[(size_t)i0*32 + t];
        uint2 r1 = vh[(size_t)i1*32 + t];
        uint2 r2 = vh[(size_t)i2*32 + t];
        uint2 r3 = vh[(size_t)i3*32 + t];
        accum(r0); accum(r1); accum(r2); accum(r3);
    }
    for (; e < s1; e++){
        int s = g_srcs[e];
        accum(vh[(size_t)s*32 + t]);
    }

    int deg = s1 - s0;
    float dc = fmaxf((float)deg, 1.f);
    float inv = 1.f / dc;
    float4 uf = *(const float4*)(g_u + (size_t)node*128 + 4*t);

    float mxf[4] = { __half2float(__low2half(mx0)), __half2float(__high2half(mx0)),
                     __half2float(__low2half(mx1)), __half2float(__high2half(mx1)) };
    float mnf[4] = { __half2float(__low2half(mn0)), __half2float(__high2half(mn0)),
                     __half2float(__low2half(mn1)), __half2float(__high2half(mn1)) };
    float mef[4] = { sm0*inv, sm1*inv, sm2*inv, sm3*inv };
    float sqf[4] = { sq0, sq1, sq2, sq3 };
    float ufv[4] = { uf.x, uf.y, uf.z, uf.w };

    float o[4][4];
    #pragma unroll
    for (int j = 0; j < 4; j++){
        o[0][j] = deg ? (ufv[j] + mxf[j]) : 0.f;
        o[1][j] = deg ? (ufv[j] + mnf[j]) : 0.f;
        o[2][j] = deg ? (ufv[j] + mef[j]) : 0.f;
        o[3][j] = sqrtf(fmaxf(sqf[j]*inv - mef[j]*mef[j], 0.f) + 1e-5f);
    }

    // blocked write: col c = a*128 + 4t + j -> chunk = a*4 + (t>>3), off = (4t)&31
    size_t base = (size_t)(node >> 7)*16*BLKH + (size_t)(node & 127)*PITCH + ((4*t) & 31);
    int csub = t >> 3;
    #pragma unroll
    for (int a = 0; a < 4; a++){
        __half2 h0 = __floats2half2_rn(o[a][0], o[a][1]);
        __half2 h1 = __floats2half2_rn(o[a][2], o[a][3]);
        uint2 pack;
        pack.x = *(uint32_t*)&h0;
        pack.y = *(uint32_t*)&h1;
        *(uint2*)(g_aggb + base + (size_t)(a*4 + csub)*BLKH) = pack;
    }

    if (t == 0){
        float ld = logf(dc + 1.f);   // DELTA = 1.0
        g_amp[node] = ld;
        g_att[node] = 1.f / ld;
    }
}

// ---------------- factored FP16 post GEMM (3-stage bulk pipeline) ------------
#define P_STAGE (4*BLKH)
#define NSTAGE 3
#define POST_SMEM_BYTES (NSTAGE*P_STAGE*2)

__global__ void __launch_bounds__(256, 1)
k_post3(int M, float* __restrict__ C)
{
    extern __shared__ __align__(16) __half smh[];
    __shared__ __align__(16) uint64_t barsto[NSTAGE];

    int tid  = threadIdx.x;
    int bi   = blockIdx.x;
    int m0   = bi * 128;
    int wid  = tid >> 5, lane = tid & 31;
    int wm   = (wid >> 1) * 32;
    int wn   = (wid & 1) * 64;
    int grp  = lane >> 2, qid = lane & 3;

    int arow  = (lane & 7) + ((lane >> 3) & 1) * 8;
    int aksel = (lane >> 4) * 8;
    int brow  = (lane & 7) + ((lane >> 4) ? 8 : 0);
    int bksel = ((lane >> 3) & 1) * 8;

    uint32_t bars[NSTAGE];
    #pragma unroll
    for (int i = 0; i < NSTAGE; i++) bars[i] = s2u(&barsto[i]);
    if (tid == 0){
        #pragma unroll
        for (int i = 0; i < NSTAGE; i++) mbar_init(bars[i], 1);
    }
    __syncthreads();

    float accC[2][8][4], accA[2][8][4], accT[2][8][4];
    #pragma unroll
    for (int mt = 0; mt < 2; mt++)
        #pragma unroll
        for (int nt = 0; nt < 8; nt++)
            #pragma unroll
            for (int q = 0; q < 4; q++){
                accC[mt][nt][q] = 0.f; accA[mt][nt][q] = 0.f; accT[mt][nt][q] = 0.f;
            }

    auto issue = [&](int t, int buf){
        uint32_t sA  = s2u(&smh[buf*P_STAGE]);
        if (t < 4){
            mbar_expect_tx(bars[buf], 2*BLKB);
            bulk_g2s(sA,        g_xb + ((size_t)bi*4 + t)*BLKH, BLKB, bars[buf]);
            bulk_g2s(sA + BLKB, g_wcb + (size_t)t*BLKH,         BLKB, bars[buf]);
        } else {
            int ka = t - 4;
            mbar_expect_tx(bars[buf], 4*BLKB);
            bulk_g2s(sA,          g_aggb + ((size_t)bi*16 + ka)*BLKH, BLKB, bars[buf]);
            bulk_g2s(sA + 1*BLKB, g_wcb + (size_t)(4  + ka)*BLKH,     BLKB, bars[buf]);
            bulk_g2s(sA + 2*BLKB, g_wcb + (size_t)(20 + ka)*BLKH,     BLKB, bars[buf]);
            bulk_g2s(sA + 3*BLKB, g_wcb + (size_t)(36 + ka)*BLKH,     BLKB, bars[buf]);
        }
    };

    const int T = 20;
    if (tid == 0){ issue(0, 0); issue(1, 1); issue(2, 2); }

    int cur = 0, ph = 0;
    for (int t = 0; t < T; t++){
        mbar_wait(bars[cur], ph);
        const __half* S = &smh[cur*P_STAGE];
        int nsets = (t < 4) ? 1 : 3;
        #pragma unroll
        for (int ks = 0; ks < 2; ks++){
            int kk = ks*16;
            uint32_t a[2][4];
            #pragma unroll
            for (int mt = 0; mt < 2; mt++){
                uint32_t addr = s2u(&S[(wm + mt*16 + arow)*PITCH + kk + aksel]);
                LDSM_X4(a[mt][0], a[mt][1], a[mt][2], a[mt][3], addr);
            }
            #pragma unroll
            for (int s = 0; s < 3; s++){
                if (s >= nsets) break;
                const __half* W = S + (1 + s)*BLKH;
                uint32_t b[8][2];
                #pragma unroll
                for (int p = 0; p < 4; p++){
                    uint32_t addr = s2u(&W[(wn + p*16 + brow)*PITCH + kk + bksel]);
                    LDSM_X4(b[2*p][0], b[2*p][1], b[2*p+1][0], b[2*p+1][1], addr);
                }
                float (*acc)[8][4] = (s == 0) ? accC : (s == 1) ? accA : accT;
                #pragma unroll
                for (int mt = 0; mt < 2; mt++)
                    #pragma unroll
                    for (int nt = 0; nt < 8; nt++)
                        MMA_F16(acc[mt][nt], a[mt][0],a[mt][1],a[mt][2],a[mt][3],
                                b[nt][0], b[nt][1]);
            }
        }
        __syncthreads();
        if (t + NSTAGE < T && tid == 0) issue(t + NSTAGE, cur);
        cur++;
        if (cur == NSTAGE){ cur = 0; ph ^= 1; }
    }

    #pragma unroll
    for (int mt = 0; mt < 2; mt++){
        int row0 = m0 + wm + mt*16 + grp;
        int row1 = row0 + 8;
        float amp0 = 0.f, att0 = 0.f, amp1 = 0.f, att1 = 0.f;
        if (row0 < M){ amp0 = g_amp[row0]; att0 = g_att[row0]; }
        if (row1 < M){ amp1 = g_amp[row1]; att1 = g_att[row1]; }
        #pragma unroll
        for (int nt = 0; nt < 8; nt++){
            int col = wn + nt*8 + 2*qid;
            float b0 = g_b_comb[col], b1 = g_b_comb[col+1];
            if (row0 < M){
                float2 v;
                v.x = accC[mt][nt][0] + amp0*accA[mt][nt][0] + att0*accT[mt][nt][0] + b0;
                v.y = accC[mt][nt][1] + amp0*accA[mt][nt][1] + att0*accT[mt][nt][1] + b1;
                *(float2*)(C + (size_t)row0*128 + col) = v;
            }
            if (row1 < M){
                float2 v;
                v.x = accC[mt][nt][2] + amp1*accA[mt][nt][2] + att1*accT[mt][nt][2] + b0;
                v.y = accC[mt][nt][3] + amp1*accA[mt][nt][3] + att1*accT[mt][nt][3] + b1;
                *(float2*)(C + (size_t)row1*128 + col) = v;
            }
        }
    }
}

// ---------------- launch: forked streams for independent chains --------------
extern "C" void kernel_launch(void* const* d_in, const int* in_sizes, int n_in,
                              void* d_out, int out_size)
{
    const float* x      = (const float*)d_in[0];
    const int*   ei     = (const int*)  d_in[1];
    const float* W_pre  = (const float*)d_in[2];
    const float* b_pre  = (const float*)d_in[3];
    const float* W_post = (const float*)d_in[4];
    const float* b_post = (const float*)d_in[5];
    const float* W_lin  = (const float*)d_in[6];
    const float* b_lin  = (const float*)d_in[7];
    float* out = (float*)d_out;

    int N = in_sizes[0] / FDIM;
    int E = in_sizes[1] / 2;
    const int* src = ei;        // edge_index[0] = x_j (source)
    const int* dst = ei + E;    // edge_index[1] = x_i (destination)

    cudaFuncSetAttribute(k_post3,
                         cudaFuncAttributeMaxDynamicSharedMemorySize, POST_SMEM_BYTES);

    int gm = (N + 127)/128;
    dim3 guv(gm, 2);

    cudaStream_t s1;
    cudaEvent_t e0, e1;
    cudaStreamCreateWithFlags(&s1, cudaStreamNonBlocking);
    cudaEventCreateWithFlags(&e0, cudaEventDisableTiming);
    cudaEventCreateWithFlags(&e1, cudaEventDisableTiming);

    // fork: side stream rooted at current position of the (captured) default stream
    cudaEventRecord(e0, 0);
    cudaStreamWaitEvent(s1, e0, 0);

    // branch A (default stream): CSR build
    k_hist   <<<(E+255)/256, 256>>>(dst, E);
    k_scan   <<<1, 1024>>>(N);
    k_scatter<<<(E+255)/256, 256>>>(src, dst, E);

    // branch B (side stream): prep -> combine -> u/v GEMM
    k_prep   <<<(N*32+255)/256, 256, 0, s1>>>(x, W_pre, W_lin, N);
    k_combine<<<KPOST+1, FDIM, 0, s1>>>(W_post, b_post, b_lin);
    k_uv_f16 <<<guv, 256, 0, s1>>>(N, b_pre);
    cudaEventRecord(e1, s1);

    // join: agg needs g_srcs (A) + g_vh/g_u (B)
    cudaStreamWaitEvent(0, e1, 0);
    k_agg<<<(N+3)/4, 128>>>(N);

    // post GEMM (needs agg + wcb/b_comb from B, ordered via join)
    k_post3<<<gm, 256, POST_SMEM_BYTES>>>(N, out);

    cudaEventDestroy(e0);
    cudaEventDestroy(e1);
    cudaStreamDestroy(s1);
}